// round 9
// baseline (speedup 1.0000x reference)
#include <cuda_runtime.h>
#include <math.h>

// Problem constants (fixed by setup_inputs)
#define Bv 64
#define Nv 3136
#define Cv 64
#define DOUT 128
#define Wv 56
#define NG 49
#define SAMPLE 784
#define ND 833            // NG + SAMPLE
#define NS 3087           // Nv - NG
#define NSR 196           // (56/4)^2
#define HIDN 512

// ---------------- scratch (static device memory; allocation-free) ----------
__device__ float g_xsn  [Bv*Nv*Cv];
__device__ float g_scores[Bv*NS];
__device__ int   g_pix  [Bv*Nv];
__device__ int   g_idx  [Bv*SAMPLE];
__device__ float g_xdown[Bv*ND*Cv];
__device__ float g_xn   [Bv*ND*Cv];
__device__ float g_posd [Bv*ND*2];
__device__ float g_segf [Bv*Nv*Cv];
__device__ float g_cnt  [Bv*Nv];
__device__ float g_fmap [Bv*Nv*Cv];
__device__ float g_xs   [Bv*NSR*Cv];
__device__ float g_q    [Bv*ND*DOUT];
__device__ float g_kb   [Bv*NSR*DOUT];
__device__ float g_vb   [Bv*NSR*DOUT];
__device__ float g_oatt [Bv*ND*DOUT];
__device__ float g_tproj[Bv*ND*DOUT];
__device__ float g_x2   [Bv*ND*DOUT];
__device__ float g_xn2  [Bv*ND*DOUT];
__device__ float g_hid  [Bv*ND*HIDN];

__device__ __forceinline__ float warp_sum(float v){
    #pragma unroll
    for (int o = 16; o; o >>= 1) v = __fadd_rn(v, __shfl_xor_sync(0xffffffffu, v, o));
    return v;
}
__device__ __forceinline__ float warp_max(float v){
    #pragma unroll
    for (int o = 16; o; o >>= 1) v = fmaxf(v, __shfl_xor_sync(0xffffffffu, v, o));
    return v;
}

// ---------------- zero segf/cnt -------------------------------------------
__global__ void zero_kernel(){
    int stride = gridDim.x * blockDim.x;
    int t = blockIdx.x * blockDim.x + threadIdx.x;
    for (int i = t; i < Bv*Nv*Cv; i += stride) g_segf[i] = 0.f;
    for (int i = t; i < Bv*Nv;    i += stride) g_cnt[i]  = 0.f;
}

// ---------------- LN(x) -> xsn (norm1) + token pixel (continuous path) -----
__global__ void ln_conf_kernel(const float* __restrict__ x, const float* __restrict__ pos,
                               const float* __restrict__ n1g, const float* __restrict__ n1b){
    int warp = (blockIdx.x * blockDim.x + threadIdx.x) >> 5;
    int lane = threadIdx.x & 31;
    if (warp >= Bv*Nv) return;
    const float* xr = x + (size_t)warp * Cv;
    float v0 = xr[lane], v1 = xr[lane+32];
    float m = warp_sum(v0 + v1) * (1.0f/64.0f);
    float d0 = v0 - m, d1 = v1 - m;
    float var = warp_sum(d0*d0 + d1*d1) * (1.0f/64.0f);
    float rstd = rsqrtf(var + 1e-5f);
    g_xsn[(size_t)warp*64 + lane]    = d0*rstd*n1g[lane]    + n1b[lane];
    g_xsn[(size_t)warp*64 + lane+32] = d1*rstd*n1g[lane+32] + n1b[lane+32];
    if (lane == 0){
        float px = fminf(fmaxf(pos[(size_t)warp*2],   0.f), 1.f) * 55.f;
        float py = fminf(fmaxf(pos[(size_t)warp*2+1], 0.f), 1.f) * 55.f;
        int xi = (int)rintf(px), yi = (int)rintf(py);   // half-to-even like jnp.round
        g_pix[warp] = xi + yi * Wv;
    }
}

// ---------------- score path: XLA-CPU semantics -----------------------------
// One thread per sampled token. Sequential in-order reduces (XLA-CPU scalar
// loop emission), rsqrt = 1/sqrt (two correctly-rounded ops), logs via double
// (emulates glibc's correctly-rounded logf). Per-op rounding, no contraction.
__global__ void score_kernel(const float* __restrict__ x,
                             const float* __restrict__ noise_u,
                             const float* __restrict__ ng, const float* __restrict__ nb,
                             const float* __restrict__ cw, const float* __restrict__ cb){
    int t = blockIdx.x * blockDim.x + threadIdx.x;
    if (t >= Bv*NS) return;
    int b = t / NS, i = t % NS;
    int n = NG + i;
    const float* xr = x + ((size_t)b*Nv + n) * Cv;
    float s = 0.f;
    for (int k = 0; k < 64; k++) s = __fadd_rn(s, xr[k]);
    float m = __fdiv_rn(s, 64.0f);
    float vs = 0.f;
    for (int k = 0; k < 64; k++){
        float d = __fsub_rn(xr[k], m);
        vs = __fadd_rn(vs, __fmul_rn(d, d));
    }
    float var = __fdiv_rn(vs, 64.0f);
    float rstd = __fdiv_rn(1.0f, sqrtf(__fadd_rn(var, 1e-5f)));   // CPU rsqrt = 1/sqrt
    float c = 0.f;
    for (int k = 0; k < 64; k++){
        float h = __fmul_rn(__fsub_rn(xr[k], m), rstd);
        float tt = __fadd_rn(__fmul_rn(h, ng[k]), nb[k]);         // g=1,b=0 identities
        c = __fadd_rn(c, __fmul_rn(tt, cw[k]));
    }
    float u = noise_u[t];
    float a1 = __fadd_rn(u, 1e-6f);
    float l1 = (float)log((double)a1);                            // correctly-rounded logf
    float inner = __fadd_rn(-l1, 1e-6f);
    float l2 = (float)log((double)inner);
    float noise = -l2;
    g_scores[t] = __fadd_rn(__fadd_rn(c, cb[0]), noise);
}

// ---------------- exact jax top-k: bitonic sort of (score desc, idx asc) ---
__global__ void topk_kernel(){
    __shared__ unsigned long long keys[4096];
    int b = blockIdx.x, tid = threadIdx.x;
    for (int i = tid; i < 4096; i += 1024){
        unsigned long long kk = ~0ULL;
        if (i < NS){
            unsigned u = __float_as_uint(g_scores[(size_t)b*NS + i]);
            u = (u & 0x80000000u) ? ~u : (u | 0x80000000u);  // ascending-ordered uint
            kk = ((unsigned long long)(~u) << 32) | (unsigned)i;  // asc key = desc score
        }
        keys[i] = kk;
    }
    __syncthreads();
    for (int k = 2; k <= 4096; k <<= 1)
        for (int j = k >> 1; j > 0; j >>= 1){
            for (int t = tid; t < 4096; t += 1024){
                int ixj = t ^ j;
                if (ixj > t){
                    bool up = ((t & k) == 0);
                    unsigned long long a = keys[t], c = keys[ixj];
                    if ((a > c) == up){ keys[t] = c; keys[ixj] = a; }
                }
            }
            __syncthreads();
        }
    for (int i = tid; i < SAMPLE; i += 1024)
        g_idx[b*SAMPLE + i] = (int)(unsigned)(keys[i] & 0xFFFFFFFFULL);
}

// ---------------- gather x_down/pos_down + LN(norm1) -> xn -----------------
__global__ void gather_ln_kernel(const float* __restrict__ x, const float* __restrict__ pos,
                                 const float* __restrict__ n1g, const float* __restrict__ n1b){
    int warp = (blockIdx.x * blockDim.x + threadIdx.x) >> 5;
    int lane = threadIdx.x & 31;
    if (warp >= Bv*ND) return;
    int b = warp / ND, j = warp % ND;
    int n = (j < NG) ? j : (NG + g_idx[b*SAMPLE + (j - NG)]);
    const float* xr = x + ((size_t)b*Nv + n) * Cv;
    float v0 = xr[lane], v1 = xr[lane+32];
    g_xdown[(size_t)warp*64 + lane]    = v0;
    g_xdown[(size_t)warp*64 + lane+32] = v1;
    float m = warp_sum(v0 + v1) * (1.0f/64.0f);
    float d0 = v0 - m, d1 = v1 - m;
    float var = warp_sum(d0*d0 + d1*d1) * (1.0f/64.0f);
    float rstd = rsqrtf(var + 1e-5f);
    g_xn[(size_t)warp*64 + lane]    = d0*rstd*n1g[lane]    + n1b[lane];
    g_xn[(size_t)warp*64 + lane+32] = d1*rstd*n1g[lane+32] + n1b[lane+32];
    if (lane < 2) g_posd[(size_t)warp*2 + lane] = pos[((size_t)b*Nv + n)*2 + lane];
}

// ---------------- token2map scatter (segment_sum) ---------------------------
__global__ void scatter_kernel(){
    int t = blockIdx.x * blockDim.x + threadIdx.x;
    if (t >= Bv*Nv*Cv) return;
    int r = t >> 6, c = t & 63;
    int b = r / Nv;
    int p = g_pix[r];
    atomicAdd(&g_segf[((size_t)b*Nv + p)*64 + c], g_xsn[t]);
    if (c == 0) atomicAdd(&g_cnt[b*Nv + p], 1.0f);
}

// ---------------- normalize + 3x3 gaussian reconstruct fused ----------------
__global__ void blur_kernel(){
    int t = blockIdx.x * blockDim.x + threadIdx.x;
    if (t >= Bv*Nv*Cv) return;
    int c = t & 63; int q = t >> 6; int hw = q % Nv; int b = q / Nv;
    int yy = hw / Wv, xx = hw % Wv;
    // gaussian 3x3, sigma=2: exp(-d2/8)/sum
    const float e1 = 0.88249690f, e2 = 0.77880078f;
    const float S  = 1.0f + 4.0f*(e1 + e2);
    const float wt[3] = {1.0f/S, e1/S, e2/S};
    float cc = g_cnt[b*Nv + hw];
    float maskc = cc > 0.f ? 1.f : 0.f;
    float featc = (g_segf[t] / (cc + 1e-6f)) * maskc;
    float bf = 0.f, bm = 0.f;
    #pragma unroll
    for (int dy = -1; dy <= 1; dy++){
        #pragma unroll
        for (int dx = -1; dx <= 1; dx++){
            int y2 = yy + dy, x2 = xx + dx;
            if (y2 >= 0 && y2 < Wv && x2 >= 0 && x2 < Wv){
                int hw2 = y2*Wv + x2;
                float cn = g_cnt[b*Nv + hw2];
                float mn = cn > 0.f ? 1.f : 0.f;
                float fn = (g_segf[((size_t)b*Nv + hw2)*64 + c] / (cn + 1e-6f)) * mn;
                float w = wt[dy*dy + dx*dx];
                bf += w * fn; bm += w * mn;
            }
        }
    }
    float fi = bf / (bm + 1e-6f);
    fi = (bm > 0.f) ? fi : 0.f;
    g_fmap[t] = featc + (1.f - maskc) * fi;
}

// ---------------- sr 4x4 stride-4 conv as tiled GEMM ------------------------
// M = Bv*196, N = 64, K = 1024 ; k = (ky*4+kx)*64 + ci
__global__ void srconv_kernel(const float* __restrict__ srw, const float* __restrict__ srb){
    __shared__ float As[16][64];
    __shared__ float Bs[16][64];
    int m0 = blockIdx.x * 64;
    int tid = threadIdx.x, tx = tid & 15, ty = tid >> 4;
    float acc[4][4] = {};
    for (int k0 = 0; k0 < 1024; k0 += 16){
        #pragma unroll
        for (int i = 0; i < 4; i++){
            int e = tid + i*256;
            int kk = e & 15, mm = e >> 4;
            int m = m0 + mm, k = k0 + kk;
            int b = m / NSR, s2 = m % NSR;
            int oy = s2 / 14, ox = s2 % 14;
            int kyx = k >> 6, ci = k & 63;
            int ky = kyx >> 2, kx = kyx & 3;
            As[kk][mm] = g_fmap[(((size_t)b*Nv) + (oy*4+ky)*Wv + (ox*4+kx))*64 + ci];
        }
        #pragma unroll
        for (int i = 0; i < 4; i++){
            int e = tid + i*256;
            int n = e & 63, kk = e >> 6;
            int k = k0 + kk;
            int kyx = k >> 6, ci = k & 63;
            Bs[kk][n] = srw[(size_t)n*1024 + ci*16 + kyx];
        }
        __syncthreads();
        #pragma unroll
        for (int kk = 0; kk < 16; kk++){
            float a[4], bb[4];
            #pragma unroll
            for (int i = 0; i < 4; i++) a[i] = As[kk][ty*4+i];
            #pragma unroll
            for (int j = 0; j < 4; j++) bb[j] = Bs[kk][tx*4+j];
            #pragma unroll
            for (int i = 0; i < 4; i++)
                #pragma unroll
                for (int j = 0; j < 4; j++) acc[i][j] += a[i]*bb[j];
        }
        __syncthreads();
    }
    #pragma unroll
    for (int i = 0; i < 4; i++)
        #pragma unroll
        for (int j = 0; j < 4; j++){
            int m = m0 + ty*4 + i, n = tx*4 + j;
            g_xs[(size_t)m*64 + n] = acc[i][j] + srb[n];
        }
}

// ---------------- generic LN kernels ----------------------------------------
__global__ void ln64_kernel(const float* __restrict__ in, float* __restrict__ outb,
                            const float* __restrict__ g, const float* __restrict__ b, int rows){
    int warp = (blockIdx.x * blockDim.x + threadIdx.x) >> 5;
    int lane = threadIdx.x & 31;
    if (warp >= rows) return;
    const float* xr = in + (size_t)warp*64;
    float v0 = xr[lane], v1 = xr[lane+32];
    float m = warp_sum(v0+v1) * (1.0f/64.0f);
    float d0 = v0-m, d1 = v1-m;
    float rstd = rsqrtf(warp_sum(d0*d0+d1*d1)*(1.0f/64.0f) + 1e-5f);
    outb[(size_t)warp*64 + lane]    = d0*rstd*g[lane]    + b[lane];
    outb[(size_t)warp*64 + lane+32] = d1*rstd*g[lane+32] + b[lane+32];
}
__global__ void ln128_kernel(const float* __restrict__ in, float* __restrict__ outb,
                             const float* __restrict__ g, const float* __restrict__ b, int rows){
    int warp = (blockIdx.x * blockDim.x + threadIdx.x) >> 5;
    int lane = threadIdx.x & 31;
    if (warp >= rows) return;
    const float* xr = in + (size_t)warp*128;
    float v[4]; float s = 0.f;
    #pragma unroll
    for (int r = 0; r < 4; r++){ v[r] = xr[lane + 32*r]; s += v[r]; }
    float m = warp_sum(s) * (1.0f/128.0f);
    float vs = 0.f;
    #pragma unroll
    for (int r = 0; r < 4; r++){ v[r] -= m; vs += v[r]*v[r]; }
    float rstd = rsqrtf(warp_sum(vs)*(1.0f/128.0f) + 1e-5f);
    #pragma unroll
    for (int r = 0; r < 4; r++){
        int d = lane + 32*r;
        outb[(size_t)warp*128 + d] = v[r]*rstd*g[d] + b[d];
    }
}

// ---------------- tiled SGEMM: C = act(A@B + bias + add) --------------------
// 64(M) x 128(N) tile, BK=16, 256 threads, 4x8 per thread, float4 smem reads.
// Requires M%64==0, N%128==0, K%16==0 (true for all call sites).
__global__ void sgemm_kernel(const float* __restrict__ A, const float* __restrict__ Bm,
                             const float* __restrict__ bias, const float* __restrict__ add,
                             float* __restrict__ C, int M, int N, int K, int act){
    __shared__ float As[16][64];
    __shared__ float Bs[16][128];
    int m0 = blockIdx.y * 64, n0 = blockIdx.x * 128;
    int tid = threadIdx.x, tx = tid & 15, ty = tid >> 4;
    float acc[4][8] = {};
    for (int k0 = 0; k0 < K; k0 += 16){
        #pragma unroll
        for (int i = 0; i < 4; i++){
            int e = tid + i*256;
            int kk = e & 15, mm = e >> 4;
            As[kk][mm] = A[(size_t)(m0+mm)*K + k0 + kk];
        }
        #pragma unroll
        for (int i = 0; i < 8; i++){
            int e = tid + i*256;
            int n = e & 127, kk = e >> 7;
            Bs[kk][n] = Bm[(size_t)(k0+kk)*N + n0 + n];
        }
        __syncthreads();
        #pragma unroll
        for (int kk = 0; kk < 16; kk++){
            float4 av = *reinterpret_cast<const float4*>(&As[kk][ty*4]);
            float4 b0 = *reinterpret_cast<const float4*>(&Bs[kk][tx*8]);
            float4 b1 = *reinterpret_cast<const float4*>(&Bs[kk][tx*8+4]);
            float a[4] = {av.x, av.y, av.z, av.w};
            float bb[8] = {b0.x, b0.y, b0.z, b0.w, b1.x, b1.y, b1.z, b1.w};
            #pragma unroll
            for (int i = 0; i < 4; i++)
                #pragma unroll
                for (int j = 0; j < 8; j++) acc[i][j] += a[i]*bb[j];
        }
        __syncthreads();
    }
    #pragma unroll
    for (int i = 0; i < 4; i++)
        #pragma unroll
        for (int j = 0; j < 8; j++){
            int m = m0 + ty*4 + i, n = n0 + tx*8 + j;
            float v = acc[i][j];
            if (bias) v += bias[n];
            if (add)  v += add[(size_t)m*N + n];
            if (act == 1) v = 0.5f * v * (1.0f + erff(v * 0.70710678118654752f)); // exact gelu
            C[(size_t)m*N + n] = v;
        }
}

// ---------------- fused cross-attention -------------------------------------
// grid.x = 14 (64 queries/block), grid.y = B*2 (batch,head). 256 threads.
#define QPW 8
#define JPAD 224
__global__ void attn_kernel(){
    extern __shared__ float sm[];
    float* Ks = sm;                         // [224][65]
    float* Vs = Ks + JPAD*65;               // [224][64] (only 196 used)
    float* Qs = Vs + JPAD*64;               // [8 warps][8 q][64]
    float* Pp = Qs + 8*QPW*64;              // [8 warps][8 q][196]
    int bh = blockIdx.y;
    int b = bh >> 1, h = bh & 1;
    int tid = threadIdx.x, lane = tid & 31, w = tid >> 5;
    for (int e = tid; e < JPAD*64; e += 256){
        int j = e >> 6, d = e & 63;
        float kv = 0.f, vv = 0.f;
        if (j < NSR){
            size_t base = ((size_t)b*NSR + j)*128 + h*64 + d;
            kv = g_kb[base]; vv = g_vb[base];
        }
        Ks[j*65 + d] = kv;
        Vs[e] = vv;
    }
    int qbase = blockIdx.x * 64 + w * QPW;
    for (int e = lane; e < QPW*64; e += 32){
        int qi = e >> 6, d = e & 63;
        int gq = qbase + qi;
        Qs[(w*QPW + qi)*64 + d] = (gq < ND) ? g_q[((size_t)b*ND + gq)*128 + h*64 + d] : 0.f;
    }
    __syncthreads();

    float acc[QPW][7];
    #pragma unroll
    for (int qi = 0; qi < QPW; qi++)
        #pragma unroll
        for (int t = 0; t < 7; t++) acc[qi][t] = 0.f;

    for (int d = 0; d < 64; d++){
        float qv[QPW];
        #pragma unroll
        for (int qi = 0; qi < QPW; qi++) qv[qi] = Qs[(w*QPW + qi)*64 + d];
        #pragma unroll
        for (int t = 0; t < 7; t++){
            float kv = Ks[(lane + 32*t)*65 + d];
            #pragma unroll
            for (int qi = 0; qi < QPW; qi++) acc[qi][t] += qv[qi]*kv;
        }
    }
    const float scale = 0.17677669529663687f;   // (DIM // NUM_HEADS)^-0.5 = 32^-0.5
    float sums[QPW];
    #pragma unroll
    for (int qi = 0; qi < QPW; qi++){
        float mx = -1e30f;
        #pragma unroll
        for (int t = 0; t < 7; t++){
            int j = lane + 32*t;
            acc[qi][t] *= scale;
            if (j < NSR) mx = fmaxf(mx, acc[qi][t]);
        }
        mx = warp_max(mx);
        float s = 0.f;
        #pragma unroll
        for (int t = 0; t < 7; t++){
            int j = lane + 32*t;
            if (j < NSR){
                float e = expf(acc[qi][t] - mx);
                Pp[(w*QPW + qi)*196 + j] = e;
                s += e;
            }
        }
        sums[qi] = warp_sum(s);
    }
    __syncwarp();
    float o0[QPW] = {}, o1[QPW] = {};
    for (int j = 0; j < NSR; j++){
        float v0 = Vs[j*64 + lane], v1 = Vs[j*64 + lane + 32];
        #pragma unroll
        for (int qi = 0; qi < QPW; qi++){
            float p = Pp[(w*QPW + qi)*196 + j];
            o0[qi] += p*v0; o1[qi] += p*v1;
        }
    }
    #pragma unroll
    for (int qi = 0; qi < QPW; qi++){
        int gq = qbase + qi;
        if (gq < ND){
            size_t base = ((size_t)b*ND + gq)*128 + h*64;
            float inv = 1.0f / sums[qi];
            g_oatt[base + lane]      = o0[qi]*inv;
            g_oatt[base + lane + 32] = o1[qi]*inv;
        }
    }
}

// ---------------- bilinear grid-sample of pos_embed, add into out -----------
__global__ void possample_kernel(const float* __restrict__ pe, float* __restrict__ out){
    int warp = (blockIdx.x * blockDim.x + threadIdx.x) >> 5;
    int lane = threadIdx.x & 31;
    if (warp >= Bv*ND) return;
    float px = g_posd[(size_t)warp*2], py = g_posd[(size_t)warp*2 + 1];
    float gx = px*2.f - 1.f, gy = py*2.f - 1.f;
    float ix = ((gx + 1.f)*56.f - 1.f)*0.5f;
    float iy = ((gy + 1.f)*56.f - 1.f)*0.5f;
    float x0 = floorf(ix), y0 = floorf(iy);
    float wx = ix - x0,   wy = iy - y0;
    float accv[4] = {};
    #pragma unroll
    for (int cy = 0; cy < 2; cy++){
        #pragma unroll
        for (int cx = 0; cx < 2; cx++){
            float xc = x0 + cx, yc = y0 + cy;
            float wgt = (cx ? wx : 1.f-wx) * (cy ? wy : 1.f-wy);
            bool valid = (xc >= 0.f) && (xc < 56.f) && (yc >= 0.f) && (yc < 56.f);
            float wv = valid ? wgt : 0.f;
            int xi = (int)fminf(fmaxf(xc, 0.f), 55.f);
            int yi = (int)fminf(fmaxf(yc, 0.f), 55.f);
            int lin = yi*56 + xi;
            #pragma unroll
            for (int r = 0; r < 4; r++)
                accv[r] += pe[(size_t)lin*128 + lane + 32*r] * wv;
        }
    }
    #pragma unroll
    for (int r = 0; r < 4; r++)
        out[(size_t)warp*128 + lane + 32*r] += accv[r];
}

// ---------------- launcher ---------------------------------------------------
extern "C" void kernel_launch(void* const* d_in, const int* in_sizes, int n_in,
                              void* d_out, int out_size){
    const float* x        = (const float*)d_in[0];
    const float* pos      = (const float*)d_in[1];
    const float* pos_embed= (const float*)d_in[2];
    const float* noise_u  = (const float*)d_in[3];
    const float* norm_g   = (const float*)d_in[4];
    const float* norm_b   = (const float*)d_in[5];
    const float* conf_w   = (const float*)d_in[6];
    const float* conf_b   = (const float*)d_in[7];
    const float* n1g      = (const float*)d_in[8];
    const float* n1b      = (const float*)d_in[9];
    const float* q_w      = (const float*)d_in[10];
    const float* k_w      = (const float*)d_in[11];
    const float* v_w      = (const float*)d_in[12];
    const float* proj_w   = (const float*)d_in[13];
    const float* proj_b   = (const float*)d_in[14];
    const float* sr_w     = (const float*)d_in[15];
    const float* sr_b     = (const float*)d_in[16];
    const float* srn_g    = (const float*)d_in[17];
    const float* srn_b    = (const float*)d_in[18];
    const float* fc_w     = (const float*)d_in[19];
    const float* fc_b     = (const float*)d_in[20];
    const float* n2g      = (const float*)d_in[21];
    const float* n2b      = (const float*)d_in[22];
    const float* fc1_w    = (const float*)d_in[23];
    const float* fc1_b    = (const float*)d_in[24];
    const float* fc2_w    = (const float*)d_in[25];
    const float* fc2_b    = (const float*)d_in[26];
    float* out = (float*)d_out;

    float *p_xn, *p_xs, *p_q, *p_oatt, *p_tproj, *p_xdown, *p_x2, *p_xn2, *p_hid, *p_kb, *p_vb;
    cudaGetSymbolAddress((void**)&p_xn,    g_xn);
    cudaGetSymbolAddress((void**)&p_xs,    g_xs);
    cudaGetSymbolAddress((void**)&p_q,     g_q);
    cudaGetSymbolAddress((void**)&p_kb,    g_kb);
    cudaGetSymbolAddress((void**)&p_vb,    g_vb);
    cudaGetSymbolAddress((void**)&p_oatt,  g_oatt);
    cudaGetSymbolAddress((void**)&p_tproj, g_tproj);
    cudaGetSymbolAddress((void**)&p_xdown, g_xdown);
    cudaGetSymbolAddress((void**)&p_x2,    g_x2);
    cudaGetSymbolAddress((void**)&p_xn2,   g_xn2);
    cudaGetSymbolAddress((void**)&p_hid,   g_hid);

    zero_kernel<<<4096, 256>>>();
    ln_conf_kernel<<<(Bv*Nv + 7)/8, 256>>>(x, pos, n1g, n1b);
    score_kernel<<<(Bv*NS + 255)/256, 256>>>(x, noise_u, norm_g, norm_b, conf_w, conf_b);
    topk_kernel<<<Bv, 1024>>>();
    gather_ln_kernel<<<(Bv*ND + 7)/8, 256>>>(x, pos, n1g, n1b);
    scatter_kernel<<<(Bv*Nv*Cv + 255)/256, 256>>>();
    blur_kernel<<<(Bv*Nv*Cv + 255)/256, 256>>>();
    srconv_kernel<<<196, 256>>>(sr_w, sr_b);
    ln64_kernel<<<(Bv*NSR + 7)/8, 256>>>(p_xs, p_xs, srn_g, srn_b, Bv*NSR);

    // q = xn @ q_w ; k = xs @ k_w ; v = xs @ v_w   (no bias)
    sgemm_kernel<<<dim3(1, (Bv*ND)/64), 256>>>(p_xn, q_w, nullptr, nullptr, p_q, Bv*ND, 128, 64, 0);
    sgemm_kernel<<<dim3(1, (Bv*NSR)/64), 256>>>(p_xs, k_w, nullptr, nullptr, p_kb, Bv*NSR, 128, 64, 0);
    sgemm_kernel<<<dim3(1, (Bv*NSR)/64), 256>>>(p_xs, v_w, nullptr, nullptr, p_vb, Bv*NSR, 128, 64, 0);

    // fused attention
    size_t attn_smem = (size_t)(JPAD*65 + JPAD*64 + 8*QPW*64 + 8*QPW*196) * sizeof(float);
    cudaFuncSetAttribute(attn_kernel, cudaFuncAttributeMaxDynamicSharedMemorySize, (int)attn_smem);
    attn_kernel<<<dim3(14, Bv*2), 256, attn_smem>>>();

    // tproj = oatt @ proj_w + proj_b ; x2 = xdown @ fc_w + fc_b + tproj
    sgemm_kernel<<<dim3(1, (Bv*ND)/64), 256>>>(p_oatt, proj_w, proj_b, nullptr, p_tproj, Bv*ND, 128, 128, 0);
    sgemm_kernel<<<dim3(1, (Bv*ND)/64), 256>>>(p_xdown, fc_w, fc_b, p_tproj, p_x2, Bv*ND, 128, 64, 0);

    ln128_kernel<<<(Bv*ND + 7)/8, 256>>>(p_x2, p_xn2, n2g, n2b, Bv*ND);

    // hid = gelu(xn2 @ fc1 + b1) ; out = x2 + hid @ fc2 + b2
    sgemm_kernel<<<dim3(4, (Bv*ND)/64), 256>>>(p_xn2, fc1_w, fc1_b, nullptr, p_hid, Bv*ND, 512, 128, 1);
    sgemm_kernel<<<dim3(1, (Bv*ND)/64), 256>>>(p_hid, fc2_w, fc2_b, p_x2, out, Bv*ND, 128, 512, 0);

    // out += grid_sample(pos_embed)
    possample_kernel<<<(Bv*ND + 7)/8, 256>>>(pos_embed, out);
}

// round 10
// speedup vs baseline: 1.2507x; 1.2507x over previous
#include <cuda_runtime.h>
#include <math.h>

// Problem constants (fixed by setup_inputs)
#define Bv 64
#define Nv 3136
#define Cv 64
#define DOUT 128
#define Wv 56
#define NG 49
#define SAMPLE 784
#define ND 833            // NG + SAMPLE
#define NS 3087           // Nv - NG
#define NSR 196           // (56/4)^2
#define HIDN 512

// ---------------- scratch (static device memory; allocation-free) ----------
__device__ float g_scores[Bv*NS];
__device__ int   g_pix  [Bv*Nv];
__device__ int   g_idx  [Bv*SAMPLE];
__device__ float g_xdown[Bv*ND*Cv];
__device__ float g_xn   [Bv*ND*Cv];
__device__ float g_posd [Bv*ND*2];
__device__ float g_segf [Bv*Nv*Cv];
__device__ float g_cnt  [Bv*Nv];
__device__ float g_fmap [Bv*Nv*Cv];
__device__ float g_xs   [Bv*NSR*Cv];
__device__ float g_q    [Bv*ND*DOUT];
__device__ float g_kb   [Bv*NSR*DOUT];
__device__ float g_vb   [Bv*NSR*DOUT];
__device__ float g_oatt [Bv*ND*DOUT];
__device__ float g_tproj[Bv*ND*DOUT];
__device__ float g_x2   [Bv*ND*DOUT];
__device__ float g_xn2  [Bv*ND*DOUT];
__device__ float g_hid  [Bv*ND*HIDN];

__device__ __forceinline__ float warp_sum(float v){
    #pragma unroll
    for (int o = 16; o; o >>= 1) v = __fadd_rn(v, __shfl_xor_sync(0xffffffffu, v, o));
    return v;
}
__device__ __forceinline__ float warp_max(float v){
    #pragma unroll
    for (int o = 16; o; o >>= 1) v = fmaxf(v, __shfl_xor_sync(0xffffffffu, v, o));
    return v;
}

// ---------------- zero segf/cnt -------------------------------------------
__global__ void zero_kernel(){
    int stride = gridDim.x * blockDim.x;
    int t = blockIdx.x * blockDim.x + threadIdx.x;
    for (int i = t; i < Bv*Nv*Cv; i += stride) g_segf[i] = 0.f;
    for (int i = t; i < Bv*Nv;    i += stride) g_cnt[i]  = 0.f;
}

// ---------------- LN(x) -> scatter directly (token2map segment_sum) --------
// Computes xsn in registers and atomically accumulates into the pixel map,
// eliminating the g_xsn round-trip entirely.
__global__ void ln_scatter_kernel(const float* __restrict__ x, const float* __restrict__ pos,
                                  const float* __restrict__ n1g, const float* __restrict__ n1b){
    int warp = (blockIdx.x * blockDim.x + threadIdx.x) >> 5;
    int lane = threadIdx.x & 31;
    if (warp >= Bv*Nv) return;
    const float* xr = x + (size_t)warp * Cv;
    float v0 = xr[lane], v1 = xr[lane+32];
    float m = warp_sum(v0 + v1) * (1.0f/64.0f);
    float d0 = v0 - m, d1 = v1 - m;
    float var = warp_sum(d0*d0 + d1*d1) * (1.0f/64.0f);
    float rstd = rsqrtf(var + 1e-5f);
    float xsn0 = d0*rstd*n1g[lane]    + n1b[lane];
    float xsn1 = d1*rstd*n1g[lane+32] + n1b[lane+32];
    int b = warp / Nv;
    int p = 0;
    if (lane == 0){
        float px = fminf(fmaxf(pos[(size_t)warp*2],   0.f), 1.f) * 55.f;
        float py = fminf(fmaxf(pos[(size_t)warp*2+1], 0.f), 1.f) * 55.f;
        p = (int)rintf(px) + (int)rintf(py) * Wv;     // half-to-even like jnp.round
    }
    p = __shfl_sync(0xffffffffu, p, 0);
    size_t base = ((size_t)b*Nv + p)*64;
    atomicAdd(&g_segf[base + lane],      xsn0);
    atomicAdd(&g_segf[base + lane + 32], xsn1);
    if (lane == 0) atomicAdd(&g_cnt[b*Nv + p], 1.0f);
}

// ---------------- score path: XLA-CPU semantics -----------------------------
__global__ void score_kernel(const float* __restrict__ x,
                             const float* __restrict__ noise_u,
                             const float* __restrict__ ng, const float* __restrict__ nb,
                             const float* __restrict__ cw, const float* __restrict__ cb){
    int t = blockIdx.x * blockDim.x + threadIdx.x;
    if (t >= Bv*NS) return;
    int b = t / NS, i = t % NS;
    int n = NG + i;
    const float* xr = x + ((size_t)b*Nv + n) * Cv;
    float s = 0.f;
    for (int k = 0; k < 64; k++) s = __fadd_rn(s, xr[k]);
    float m = __fdiv_rn(s, 64.0f);
    float vs = 0.f;
    for (int k = 0; k < 64; k++){
        float d = __fsub_rn(xr[k], m);
        vs = __fadd_rn(vs, __fmul_rn(d, d));
    }
    float var = __fdiv_rn(vs, 64.0f);
    float rstd = __fdiv_rn(1.0f, sqrtf(__fadd_rn(var, 1e-5f)));   // CPU rsqrt = 1/sqrt
    float c = 0.f;
    for (int k = 0; k < 64; k++){
        float h = __fmul_rn(__fsub_rn(xr[k], m), rstd);
        float tt = __fadd_rn(__fmul_rn(h, ng[k]), nb[k]);
        c = __fadd_rn(c, __fmul_rn(tt, cw[k]));
    }
    float u = noise_u[t];
    float a1 = __fadd_rn(u, 1e-6f);
    float l1 = (float)log((double)a1);                            // correctly-rounded logf
    float inner = __fadd_rn(-l1, 1e-6f);
    float l2 = (float)log((double)inner);
    float noise = -l2;
    g_scores[t] = __fadd_rn(__fadd_rn(c, cb[0]), noise);
}

// ---------------- exact jax top-k: bitonic sort of (score desc, idx asc) ---
__global__ void topk_kernel(){
    __shared__ unsigned long long keys[4096];
    int b = blockIdx.x, tid = threadIdx.x;
    for (int i = tid; i < 4096; i += 1024){
        unsigned long long kk = ~0ULL;
        if (i < NS){
            unsigned u = __float_as_uint(g_scores[(size_t)b*NS + i]);
            u = (u & 0x80000000u) ? ~u : (u | 0x80000000u);
            kk = ((unsigned long long)(~u) << 32) | (unsigned)i;
        }
        keys[i] = kk;
    }
    __syncthreads();
    for (int k = 2; k <= 4096; k <<= 1)
        for (int j = k >> 1; j > 0; j >>= 1){
            for (int t = tid; t < 4096; t += 1024){
                int ixj = t ^ j;
                if (ixj > t){
                    bool up = ((t & k) == 0);
                    unsigned long long a = keys[t], c = keys[ixj];
                    if ((a > c) == up){ keys[t] = c; keys[ixj] = a; }
                }
            }
            __syncthreads();
        }
    for (int i = tid; i < SAMPLE; i += 1024)
        g_idx[b*SAMPLE + i] = (int)(unsigned)(keys[i] & 0xFFFFFFFFULL);
}

// ---------------- gather x_down/pos_down + LN(norm1) -> xn -----------------
__global__ void gather_ln_kernel(const float* __restrict__ x, const float* __restrict__ pos,
                                 const float* __restrict__ n1g, const float* __restrict__ n1b){
    int warp = (blockIdx.x * blockDim.x + threadIdx.x) >> 5;
    int lane = threadIdx.x & 31;
    if (warp >= Bv*ND) return;
    int b = warp / ND, j = warp % ND;
    int n = (j < NG) ? j : (NG + g_idx[b*SAMPLE + (j - NG)]);
    const float* xr = x + ((size_t)b*Nv + n) * Cv;
    float v0 = xr[lane], v1 = xr[lane+32];
    g_xdown[(size_t)warp*64 + lane]    = v0;
    g_xdown[(size_t)warp*64 + lane+32] = v1;
    float m = warp_sum(v0 + v1) * (1.0f/64.0f);
    float d0 = v0 - m, d1 = v1 - m;
    float var = warp_sum(d0*d0 + d1*d1) * (1.0f/64.0f);
    float rstd = rsqrtf(var + 1e-5f);
    g_xn[(size_t)warp*64 + lane]    = d0*rstd*n1g[lane]    + n1b[lane];
    g_xn[(size_t)warp*64 + lane+32] = d1*rstd*n1g[lane+32] + n1b[lane+32];
    if (lane < 2) g_posd[(size_t)warp*2 + lane] = pos[((size_t)b*Nv + n)*2 + lane];
}

// ---------------- normalize + 3x3 gaussian reconstruct fused ----------------
__global__ void blur_kernel(){
    int t = blockIdx.x * blockDim.x + threadIdx.x;
    if (t >= Bv*Nv*Cv) return;
    int c = t & 63; int q = t >> 6; int hw = q % Nv; int b = q / Nv;
    int yy = hw / Wv, xx = hw % Wv;
    const float e1 = 0.88249690f, e2 = 0.77880078f;
    const float S  = 1.0f + 4.0f*(e1 + e2);
    const float wt[3] = {1.0f/S, e1/S, e2/S};
    float cc = g_cnt[b*Nv + hw];
    float maskc = cc > 0.f ? 1.f : 0.f;
    float featc = (g_segf[t] / (cc + 1e-6f)) * maskc;
    float bf = 0.f, bm = 0.f;
    #pragma unroll
    for (int dy = -1; dy <= 1; dy++){
        #pragma unroll
        for (int dx = -1; dx <= 1; dx++){
            int y2 = yy + dy, x2 = xx + dx;
            if (y2 >= 0 && y2 < Wv && x2 >= 0 && x2 < Wv){
                int hw2 = y2*Wv + x2;
                float cn = g_cnt[b*Nv + hw2];
                float mn = cn > 0.f ? 1.f : 0.f;
                float fn = (g_segf[((size_t)b*Nv + hw2)*64 + c] / (cn + 1e-6f)) * mn;
                float w = wt[dy*dy + dx*dx];
                bf += w * fn; bm += w * mn;
            }
        }
    }
    float fi = bf / (bm + 1e-6f);
    fi = (bm > 0.f) ? fi : 0.f;
    g_fmap[t] = featc + (1.f - maskc) * fi;
}

// ---------------- sr 4x4 stride-4 conv as tiled GEMM ------------------------
// M = Bv*196, N = 64, K = 1024 ; k = (ky*4+kx)*64 + ci
__global__ void srconv_kernel(const float* __restrict__ srw, const float* __restrict__ srb){
    __shared__ float As[16][64];
    __shared__ float Bs[16][64];
    int m0 = blockIdx.x * 64;
    int tid = threadIdx.x, tx = tid & 15, ty = tid >> 4;
    float acc[4][4] = {};
    for (int k0 = 0; k0 < 1024; k0 += 16){
        #pragma unroll
        for (int i = 0; i < 4; i++){
            int e = tid + i*256;
            int kk = e & 15, mm = e >> 4;
            int m = m0 + mm, k = k0 + kk;
            int b = m / NSR, s2 = m % NSR;
            int oy = s2 / 14, ox = s2 % 14;
            int kyx = k >> 6, ci = k & 63;
            int ky = kyx >> 2, kx = kyx & 3;
            As[kk][mm] = g_fmap[(((size_t)b*Nv) + (oy*4+ky)*Wv + (ox*4+kx))*64 + ci];
        }
        #pragma unroll
        for (int i = 0; i < 4; i++){
            int e = tid + i*256;
            int n = e & 63, kk = e >> 6;
            int k = k0 + kk;
            int kyx = k >> 6, ci = k & 63;
            Bs[kk][n] = srw[(size_t)n*1024 + ci*16 + kyx];
        }
        __syncthreads();
        #pragma unroll
        for (int kk = 0; kk < 16; kk++){
            float a[4], bb[4];
            #pragma unroll
            for (int i = 0; i < 4; i++) a[i] = As[kk][ty*4+i];
            #pragma unroll
            for (int j = 0; j < 4; j++) bb[j] = Bs[kk][tx*4+j];
            #pragma unroll
            for (int i = 0; i < 4; i++)
                #pragma unroll
                for (int j = 0; j < 4; j++) acc[i][j] += a[i]*bb[j];
        }
        __syncthreads();
    }
    #pragma unroll
    for (int i = 0; i < 4; i++)
        #pragma unroll
        for (int j = 0; j < 4; j++){
            int m = m0 + ty*4 + i, n = tx*4 + j;
            g_xs[(size_t)m*64 + n] = acc[i][j] + srb[n];
        }
}

// ---------------- generic LN kernels ----------------------------------------
__global__ void ln64_kernel(const float* __restrict__ in, float* __restrict__ outb,
                            const float* __restrict__ g, const float* __restrict__ b, int rows){
    int warp = (blockIdx.x * blockDim.x + threadIdx.x) >> 5;
    int lane = threadIdx.x & 31;
    if (warp >= rows) return;
    const float* xr = in + (size_t)warp*64;
    float v0 = xr[lane], v1 = xr[lane+32];
    float m = warp_sum(v0+v1) * (1.0f/64.0f);
    float d0 = v0-m, d1 = v1-m;
    float rstd = rsqrtf(warp_sum(d0*d0+d1*d1)*(1.0f/64.0f) + 1e-5f);
    outb[(size_t)warp*64 + lane]    = d0*rstd*g[lane]    + b[lane];
    outb[(size_t)warp*64 + lane+32] = d1*rstd*g[lane+32] + b[lane+32];
}
__global__ void ln128_kernel(const float* __restrict__ in, float* __restrict__ outb,
                             const float* __restrict__ g, const float* __restrict__ b, int rows){
    int warp = (blockIdx.x * blockDim.x + threadIdx.x) >> 5;
    int lane = threadIdx.x & 31;
    if (warp >= rows) return;
    const float* xr = in + (size_t)warp*128;
    float v[4]; float s = 0.f;
    #pragma unroll
    for (int r = 0; r < 4; r++){ v[r] = xr[lane + 32*r]; s += v[r]; }
    float m = warp_sum(s) * (1.0f/128.0f);
    float vs = 0.f;
    #pragma unroll
    for (int r = 0; r < 4; r++){ v[r] -= m; vs += v[r]*v[r]; }
    float rstd = rsqrtf(warp_sum(vs)*(1.0f/128.0f) + 1e-5f);
    #pragma unroll
    for (int r = 0; r < 4; r++){
        int d = lane + 32*r;
        outb[(size_t)warp*128 + d] = v[r]*rstd*g[d] + b[d];
    }
}

// ---------------- tiled SGEMM v2: C = act(A@B + bias + add) -----------------
// 64(M) x 128(N) tile, BK=8, 128 threads, 8x8 microtile, double-buffered smem
// with register prefetch. Requires M%64==0, N%128==0, K%8==0, K>=8.
__global__ void sgemm_kernel(const float* __restrict__ A, const float* __restrict__ Bm,
                             const float* __restrict__ bias, const float* __restrict__ add,
                             float* __restrict__ C, int M, int N, int K, int act){
    __shared__ float As[2][8][64];
    __shared__ float Bs[2][8][128];
    int m0 = blockIdx.y * 64, n0 = blockIdx.x * 128;
    int tid = threadIdx.x;               // 128 threads
    int tx = tid & 15, ty = tid >> 4;    // 16 x 8 thread grid
    int am = tid >> 1, ak = (tid & 1) * 4;   // A loader: row am, k-quad ak
    int bkk = tid >> 4, bn = (tid & 15) * 8; // B loader: k-row bkk, n-octet bn

    const float* Arow = A + (size_t)(m0 + am) * K;

    float4 ra  = *(const float4*)&Arow[ak];
    float4 rb0 = *(const float4*)&Bm[(size_t)bkk*N + n0 + bn];
    float4 rb1 = *(const float4*)&Bm[(size_t)bkk*N + n0 + bn + 4];
    As[0][ak+0][am] = ra.x; As[0][ak+1][am] = ra.y;
    As[0][ak+2][am] = ra.z; As[0][ak+3][am] = ra.w;
    *(float4*)&Bs[0][bkk][bn]   = rb0;
    *(float4*)&Bs[0][bkk][bn+4] = rb1;
    __syncthreads();

    float acc[8][8] = {};
    int nk = K >> 3;
    for (int kt = 0; kt < nk; kt++){
        int cur = kt & 1, nxt = cur ^ 1;
        if (kt + 1 < nk){
            int k0 = (kt + 1) << 3;
            ra  = *(const float4*)&Arow[k0 + ak];
            rb0 = *(const float4*)&Bm[(size_t)(k0 + bkk)*N + n0 + bn];
            rb1 = *(const float4*)&Bm[(size_t)(k0 + bkk)*N + n0 + bn + 4];
        }
        #pragma unroll
        for (int kk = 0; kk < 8; kk++){
            float a[8], b[8];
            *(float4*)&a[0] = *(const float4*)&As[cur][kk][ty*8];
            *(float4*)&a[4] = *(const float4*)&As[cur][kk][ty*8 + 4];
            *(float4*)&b[0] = *(const float4*)&Bs[cur][kk][tx*8];
            *(float4*)&b[4] = *(const float4*)&Bs[cur][kk][tx*8 + 4];
            #pragma unroll
            for (int i = 0; i < 8; i++)
                #pragma unroll
                for (int j = 0; j < 8; j++) acc[i][j] += a[i]*b[j];
        }
        if (kt + 1 < nk){
            As[nxt][ak+0][am] = ra.x; As[nxt][ak+1][am] = ra.y;
            As[nxt][ak+2][am] = ra.z; As[nxt][ak+3][am] = ra.w;
            *(float4*)&Bs[nxt][bkk][bn]   = rb0;
            *(float4*)&Bs[nxt][bkk][bn+4] = rb1;
            __syncthreads();
        }
    }
    #pragma unroll
    for (int i = 0; i < 8; i++){
        int m = m0 + ty*8 + i;
        #pragma unroll
        for (int j = 0; j < 8; j++){
            int n = n0 + tx*8 + j;
            float v = acc[i][j];
            if (bias) v += bias[n];
            if (add)  v += add[(size_t)m*N + n];
            if (act == 1) v = 0.5f * v * (1.0f + erff(v * 0.70710678118654752f)); // exact gelu
            C[(size_t)m*N + n] = v;
        }
    }
}

// ---------------- fused cross-attention -------------------------------------
// grid.x = 14 (64 queries/block), grid.y = B*2 (batch,head). 256 threads.
#define QPW 8
#define JPAD 224
__global__ void attn_kernel(){
    extern __shared__ float sm[];
    float* Ks = sm;                         // [224][65]
    float* Vs = Ks + JPAD*65;               // [224][64] (only 196 used)
    float* Qs = Vs + JPAD*64;               // [8 warps][8 q][64]
    float* Pp = Qs + 8*QPW*64;              // [8 warps][8 q][196]
    int bh = blockIdx.y;
    int b = bh >> 1, h = bh & 1;
    int tid = threadIdx.x, lane = tid & 31, w = tid >> 5;
    for (int e = tid; e < JPAD*64; e += 256){
        int j = e >> 6, d = e & 63;
        float kv = 0.f, vv = 0.f;
        if (j < NSR){
            size_t base = ((size_t)b*NSR + j)*128 + h*64 + d;
            kv = g_kb[base]; vv = g_vb[base];
        }
        Ks[j*65 + d] = kv;
        Vs[e] = vv;
    }
    int qbase = blockIdx.x * 64 + w * QPW;
    for (int e = lane; e < QPW*64; e += 32){
        int qi = e >> 6, d = e & 63;
        int gq = qbase + qi;
        Qs[(w*QPW + qi)*64 + d] = (gq < ND) ? g_q[((size_t)b*ND + gq)*128 + h*64 + d] : 0.f;
    }
    __syncthreads();

    float acc[QPW][7];
    #pragma unroll
    for (int qi = 0; qi < QPW; qi++)
        #pragma unroll
        for (int t = 0; t < 7; t++) acc[qi][t] = 0.f;

    for (int d = 0; d < 64; d++){
        float qv[QPW];
        #pragma unroll
        for (int qi = 0; qi < QPW; qi++) qv[qi] = Qs[(w*QPW + qi)*64 + d];
        #pragma unroll
        for (int t = 0; t < 7; t++){
            float kv = Ks[(lane + 32*t)*65 + d];
            #pragma unroll
            for (int qi = 0; qi < QPW; qi++) acc[qi][t] += qv[qi]*kv;
        }
    }
    const float scale = 0.17677669529663687f;   // 32^-0.5
    float sums[QPW];
    #pragma unroll
    for (int qi = 0; qi < QPW; qi++){
        float mx = -1e30f;
        #pragma unroll
        for (int t = 0; t < 7; t++){
            int j = lane + 32*t;
            acc[qi][t] *= scale;
            if (j < NSR) mx = fmaxf(mx, acc[qi][t]);
        }
        mx = warp_max(mx);
        float s = 0.f;
        #pragma unroll
        for (int t = 0; t < 7; t++){
            int j = lane + 32*t;
            if (j < NSR){
                float e = expf(acc[qi][t] - mx);
                Pp[(w*QPW + qi)*196 + j] = e;
                s += e;
            }
        }
        sums[qi] = warp_sum(s);
    }
    __syncwarp();
    float o0[QPW] = {}, o1[QPW] = {};
    for (int j = 0; j < NSR; j++){
        float v0 = Vs[j*64 + lane], v1 = Vs[j*64 + lane + 32];
        #pragma unroll
        for (int qi = 0; qi < QPW; qi++){
            float p = Pp[(w*QPW + qi)*196 + j];
            o0[qi] += p*v0; o1[qi] += p*v1;
        }
    }
    #pragma unroll
    for (int qi = 0; qi < QPW; qi++){
        int gq = qbase + qi;
        if (gq < ND){
            size_t base = ((size_t)b*ND + gq)*128 + h*64;
            float inv = 1.0f / sums[qi];
            g_oatt[base + lane]      = o0[qi]*inv;
            g_oatt[base + lane + 32] = o1[qi]*inv;
        }
    }
}

// ---------------- bilinear grid-sample of pos_embed, add into out -----------
__global__ void possample_kernel(const float* __restrict__ pe, float* __restrict__ out){
    int warp = (blockIdx.x * blockDim.x + threadIdx.x) >> 5;
    int lane = threadIdx.x & 31;
    if (warp >= Bv*ND) return;
    float px = g_posd[(size_t)warp*2], py = g_posd[(size_t)warp*2 + 1];
    float gx = px*2.f - 1.f, gy = py*2.f - 1.f;
    float ix = ((gx + 1.f)*56.f - 1.f)*0.5f;
    float iy = ((gy + 1.f)*56.f - 1.f)*0.5f;
    float x0 = floorf(ix), y0 = floorf(iy);
    float wx = ix - x0,   wy = iy - y0;
    float accv[4] = {};
    #pragma unroll
    for (int cy = 0; cy < 2; cy++){
        #pragma unroll
        for (int cx = 0; cx < 2; cx++){
            float xc = x0 + cx, yc = y0 + cy;
            float wgt = (cx ? wx : 1.f-wx) * (cy ? wy : 1.f-wy);
            bool valid = (xc >= 0.f) && (xc < 56.f) && (yc >= 0.f) && (yc < 56.f);
            float wv = valid ? wgt : 0.f;
            int xi = (int)fminf(fmaxf(xc, 0.f), 55.f);
            int yi = (int)fminf(fmaxf(yc, 0.f), 55.f);
            int lin = yi*56 + xi;
            #pragma unroll
            for (int r = 0; r < 4; r++)
                accv[r] += pe[(size_t)lin*128 + lane + 32*r] * wv;
        }
    }
    #pragma unroll
    for (int r = 0; r < 4; r++)
        out[(size_t)warp*128 + lane + 32*r] += accv[r];
}

// ---------------- launcher ---------------------------------------------------
extern "C" void kernel_launch(void* const* d_in, const int* in_sizes, int n_in,
                              void* d_out, int out_size){
    const float* x        = (const float*)d_in[0];
    const float* pos      = (const float*)d_in[1];
    const float* pos_embed= (const float*)d_in[2];
    const float* noise_u  = (const float*)d_in[3];
    const float* norm_g   = (const float*)d_in[4];
    const float* norm_b   = (const float*)d_in[5];
    const float* conf_w   = (const float*)d_in[6];
    const float* conf_b   = (const float*)d_in[7];
    const float* n1g      = (const float*)d_in[8];
    const float* n1b      = (const float*)d_in[9];
    const float* q_w      = (const float*)d_in[10];
    const float* k_w      = (const float*)d_in[11];
    const float* v_w      = (const float*)d_in[12];
    const float* proj_w   = (const float*)d_in[13];
    const float* proj_b   = (const float*)d_in[14];
    const float* sr_w     = (const float*)d_in[15];
    const float* sr_b     = (const float*)d_in[16];
    const float* srn_g    = (const float*)d_in[17];
    const float* srn_b    = (const float*)d_in[18];
    const float* fc_w     = (const float*)d_in[19];
    const float* fc_b     = (const float*)d_in[20];
    const float* n2g      = (const float*)d_in[21];
    const float* n2b      = (const float*)d_in[22];
    const float* fc1_w    = (const float*)d_in[23];
    const float* fc1_b    = (const float*)d_in[24];
    const float* fc2_w    = (const float*)d_in[25];
    const float* fc2_b    = (const float*)d_in[26];
    float* out = (float*)d_out;

    float *p_xn, *p_xs, *p_q, *p_oatt, *p_tproj, *p_xdown, *p_x2, *p_xn2, *p_hid, *p_kb, *p_vb;
    cudaGetSymbolAddress((void**)&p_xn,    g_xn);
    cudaGetSymbolAddress((void**)&p_xs,    g_xs);
    cudaGetSymbolAddress((void**)&p_q,     g_q);
    cudaGetSymbolAddress((void**)&p_kb,    g_kb);
    cudaGetSymbolAddress((void**)&p_vb,    g_vb);
    cudaGetSymbolAddress((void**)&p_oatt,  g_oatt);
    cudaGetSymbolAddress((void**)&p_tproj, g_tproj);
    cudaGetSymbolAddress((void**)&p_xdown, g_xdown);
    cudaGetSymbolAddress((void**)&p_x2,    g_x2);
    cudaGetSymbolAddress((void**)&p_xn2,   g_xn2);
    cudaGetSymbolAddress((void**)&p_hid,   g_hid);

    zero_kernel<<<4096, 256>>>();
    ln_scatter_kernel<<<(Bv*Nv + 7)/8, 256>>>(x, pos, n1g, n1b);
    score_kernel<<<(Bv*NS + 255)/256, 256>>>(x, noise_u, norm_g, norm_b, conf_w, conf_b);
    topk_kernel<<<Bv, 1024>>>();
    gather_ln_kernel<<<(Bv*ND + 7)/8, 256>>>(x, pos, n1g, n1b);
    blur_kernel<<<(Bv*Nv*Cv + 255)/256, 256>>>();
    srconv_kernel<<<196, 256>>>(sr_w, sr_b);
    ln64_kernel<<<(Bv*NSR + 7)/8, 256>>>(p_xs, p_xs, srn_g, srn_b, Bv*NSR);

    // q = xn @ q_w ; k = xs @ k_w ; v = xs @ v_w   (no bias)
    sgemm_kernel<<<dim3(1, (Bv*ND)/64), 128>>>(p_xn, q_w, nullptr, nullptr, p_q, Bv*ND, 128, 64, 0);
    sgemm_kernel<<<dim3(1, (Bv*NSR)/64), 128>>>(p_xs, k_w, nullptr, nullptr, p_kb, Bv*NSR, 128, 64, 0);
    sgemm_kernel<<<dim3(1, (Bv*NSR)/64), 128>>>(p_xs, v_w, nullptr, nullptr, p_vb, Bv*NSR, 128, 64, 0);

    // fused attention
    size_t attn_smem = (size_t)(JPAD*65 + JPAD*64 + 8*QPW*64 + 8*QPW*196) * sizeof(float);
    cudaFuncSetAttribute(attn_kernel, cudaFuncAttributeMaxDynamicSharedMemorySize, (int)attn_smem);
    attn_kernel<<<dim3(14, Bv*2), 256, attn_smem>>>();

    // tproj = oatt @ proj_w + proj_b ; x2 = xdown @ fc_w + fc_b + tproj
    sgemm_kernel<<<dim3(1, (Bv*ND)/64), 128>>>(p_oatt, proj_w, proj_b, nullptr, p_tproj, Bv*ND, 128, 128, 0);
    sgemm_kernel<<<dim3(1, (Bv*ND)/64), 128>>>(p_xdown, fc_w, fc_b, p_tproj, p_x2, Bv*ND, 128, 64, 0);

    ln128_kernel<<<(Bv*ND + 7)/8, 256>>>(p_x2, p_xn2, n2g, n2b, Bv*ND);

    // hid = gelu(xn2 @ fc1 + b1) ; out = x2 + hid @ fc2 + b2
    sgemm_kernel<<<dim3(4, (Bv*ND)/64), 128>>>(p_xn2, fc1_w, fc1_b, nullptr, p_hid, Bv*ND, 512, 128, 1);
    sgemm_kernel<<<dim3(1, (Bv*ND)/64), 128>>>(p_hid, fc2_w, fc2_b, p_x2, out, Bv*ND, 128, 512, 0);

    // out += grid_sample(pos_embed)
    possample_kernel<<<(Bv*ND + 7)/8, 256>>>(pos_embed, out);
}

// round 11
// speedup vs baseline: 1.3925x; 1.1134x over previous
#include <cuda_runtime.h>
#include <cuda_bf16.h>
#include <math.h>

typedef unsigned int uint32;

// Problem constants (fixed by setup_inputs)
#define Bv 64
#define Nv 3136
#define Cv 64
#define DOUT 128
#define Wv 56
#define NG 49
#define SAMPLE 784
#define ND 833            // NG + SAMPLE
#define NS 3087           // Nv - NG
#define NSR 196           // (56/4)^2
#define HIDN 512
#define MROWS (Bv*ND)     // 53312

// ---------------- scratch (static device memory; allocation-free) ----------
__device__ float g_scores[Bv*NS];
__device__ int   g_idx  [Bv*SAMPLE];
__device__ float g_xdown[Bv*ND*Cv];
__device__ float g_xn   [Bv*ND*Cv];
__device__ float g_posd [Bv*ND*2];
__device__ float g_segf [Bv*Nv*Cv];
__device__ float g_cnt  [Bv*Nv];
__device__ float g_fmap [Bv*Nv*Cv];
__device__ float g_xs   [Bv*NSR*Cv];
__device__ float g_q    [Bv*ND*DOUT];
__device__ float g_kb   [Bv*NSR*DOUT];
__device__ float g_vb   [Bv*NSR*DOUT];
__device__ float g_oatt [Bv*ND*DOUT];
__device__ float g_tproj[Bv*ND*DOUT];
__device__ float g_x2   [Bv*ND*DOUT];
// bf16-split operands for tensor-core MLP
__device__ __align__(16) __nv_bfloat16 g_xn2h[MROWS*DOUT];
__device__ __align__(16) __nv_bfloat16 g_xn2l[MROWS*DOUT];
__device__ __align__(16) __nv_bfloat16 g_hidh[(size_t)MROWS*HIDN];
__device__ __align__(16) __nv_bfloat16 g_hidl[(size_t)MROWS*HIDN];
__device__ __align__(16) __nv_bfloat16 g_w1h[HIDN*DOUT];   // [n][k] n<512,k<128
__device__ __align__(16) __nv_bfloat16 g_w1l[HIDN*DOUT];
__device__ __align__(16) __nv_bfloat16 g_w2h[DOUT*HIDN];   // [n][k] n<128,k<512
__device__ __align__(16) __nv_bfloat16 g_w2l[DOUT*HIDN];

__device__ __forceinline__ float warp_sum(float v){
    #pragma unroll
    for (int o = 16; o; o >>= 1) v = __fadd_rn(v, __shfl_xor_sync(0xffffffffu, v, o));
    return v;
}
__device__ __forceinline__ float warp_max(float v){
    #pragma unroll
    for (int o = 16; o; o >>= 1) v = fmaxf(v, __shfl_xor_sync(0xffffffffu, v, o));
    return v;
}
__device__ __forceinline__ void bsplit(float v, __nv_bfloat16& h, __nv_bfloat16& l){
    h = __float2bfloat16(v);
    l = __float2bfloat16(v - __bfloat162float(h));
}

// ---------------- zero segf/cnt -------------------------------------------
__global__ void zero_kernel(){
    int stride = gridDim.x * blockDim.x;
    int t = blockIdx.x * blockDim.x + threadIdx.x;
    for (int i = t; i < Bv*Nv*Cv; i += stride) g_segf[i] = 0.f;
    for (int i = t; i < Bv*Nv;    i += stride) g_cnt[i]  = 0.f;
}

// ---------------- LN(x) -> scatter directly (token2map segment_sum) --------
__global__ void ln_scatter_kernel(const float* __restrict__ x, const float* __restrict__ pos,
                                  const float* __restrict__ n1g, const float* __restrict__ n1b){
    int warp = (blockIdx.x * blockDim.x + threadIdx.x) >> 5;
    int lane = threadIdx.x & 31;
    if (warp >= Bv*Nv) return;
    const float* xr = x + (size_t)warp * Cv;
    float v0 = xr[lane], v1 = xr[lane+32];
    float m = warp_sum(v0 + v1) * (1.0f/64.0f);
    float d0 = v0 - m, d1 = v1 - m;
    float var = warp_sum(d0*d0 + d1*d1) * (1.0f/64.0f);
    float rstd = rsqrtf(var + 1e-5f);
    float xsn0 = d0*rstd*n1g[lane]    + n1b[lane];
    float xsn1 = d1*rstd*n1g[lane+32] + n1b[lane+32];
    int b = warp / Nv;
    int p = 0;
    if (lane == 0){
        float px = fminf(fmaxf(pos[(size_t)warp*2],   0.f), 1.f) * 55.f;
        float py = fminf(fmaxf(pos[(size_t)warp*2+1], 0.f), 1.f) * 55.f;
        p = (int)rintf(px) + (int)rintf(py) * Wv;     // half-to-even like jnp.round
    }
    p = __shfl_sync(0xffffffffu, p, 0);
    size_t base = ((size_t)b*Nv + p)*64;
    atomicAdd(&g_segf[base + lane],      xsn0);
    atomicAdd(&g_segf[base + lane + 32], xsn1);
    if (lane == 0) atomicAdd(&g_cnt[b*Nv + p], 1.0f);
}

// ---------------- score path: XLA-CPU semantics -----------------------------
__global__ void score_kernel(const float* __restrict__ x,
                             const float* __restrict__ noise_u,
                             const float* __restrict__ ng, const float* __restrict__ nb,
                             const float* __restrict__ cw, const float* __restrict__ cb){
    int t = blockIdx.x * blockDim.x + threadIdx.x;
    if (t >= Bv*NS) return;
    int b = t / NS, i = t % NS;
    int n = NG + i;
    const float* xr = x + ((size_t)b*Nv + n) * Cv;
    float s = 0.f;
    for (int k = 0; k < 64; k++) s = __fadd_rn(s, xr[k]);
    float m = __fdiv_rn(s, 64.0f);
    float vs = 0.f;
    for (int k = 0; k < 64; k++){
        float d = __fsub_rn(xr[k], m);
        vs = __fadd_rn(vs, __fmul_rn(d, d));
    }
    float var = __fdiv_rn(vs, 64.0f);
    float rstd = __fdiv_rn(1.0f, sqrtf(__fadd_rn(var, 1e-5f)));   // CPU rsqrt = 1/sqrt
    float c = 0.f;
    for (int k = 0; k < 64; k++){
        float h = __fmul_rn(__fsub_rn(xr[k], m), rstd);
        float tt = __fadd_rn(__fmul_rn(h, ng[k]), nb[k]);
        c = __fadd_rn(c, __fmul_rn(tt, cw[k]));
    }
    float u = noise_u[t];
    float a1 = __fadd_rn(u, 1e-6f);
    float l1 = (float)log((double)a1);
    float inner = __fadd_rn(-l1, 1e-6f);
    float l2 = (float)log((double)inner);
    float noise = -l2;
    g_scores[t] = __fadd_rn(__fadd_rn(c, cb[0]), noise);
}

// ---------------- exact jax top-k: bitonic sort of (score desc, idx asc) ---
__global__ void topk_kernel(){
    __shared__ unsigned long long keys[4096];
    int b = blockIdx.x, tid = threadIdx.x;
    for (int i = tid; i < 4096; i += 1024){
        unsigned long long kk = ~0ULL;
        if (i < NS){
            unsigned u = __float_as_uint(g_scores[(size_t)b*NS + i]);
            u = (u & 0x80000000u) ? ~u : (u | 0x80000000u);
            kk = ((unsigned long long)(~u) << 32) | (unsigned)i;
        }
        keys[i] = kk;
    }
    __syncthreads();
    for (int k = 2; k <= 4096; k <<= 1)
        for (int j = k >> 1; j > 0; j >>= 1){
            for (int t = tid; t < 4096; t += 1024){
                int ixj = t ^ j;
                if (ixj > t){
                    bool up = ((t & k) == 0);
                    unsigned long long a = keys[t], c = keys[ixj];
                    if ((a > c) == up){ keys[t] = c; keys[ixj] = a; }
                }
            }
            __syncthreads();
        }
    for (int i = tid; i < SAMPLE; i += 1024)
        g_idx[b*SAMPLE + i] = (int)(unsigned)(keys[i] & 0xFFFFFFFFULL);
}

// ---------------- gather x_down/pos_down + LN(norm1) -> xn -----------------
__global__ void gather_ln_kernel(const float* __restrict__ x, const float* __restrict__ pos,
                                 const float* __restrict__ n1g, const float* __restrict__ n1b){
    int warp = (blockIdx.x * blockDim.x + threadIdx.x) >> 5;
    int lane = threadIdx.x & 31;
    if (warp >= Bv*ND) return;
    int b = warp / ND, j = warp % ND;
    int n = (j < NG) ? j : (NG + g_idx[b*SAMPLE + (j - NG)]);
    const float* xr = x + ((size_t)b*Nv + n) * Cv;
    float v0 = xr[lane], v1 = xr[lane+32];
    g_xdown[(size_t)warp*64 + lane]    = v0;
    g_xdown[(size_t)warp*64 + lane+32] = v1;
    float m = warp_sum(v0 + v1) * (1.0f/64.0f);
    float d0 = v0 - m, d1 = v1 - m;
    float var = warp_sum(d0*d0 + d1*d1) * (1.0f/64.0f);
    float rstd = rsqrtf(var + 1e-5f);
    g_xn[(size_t)warp*64 + lane]    = d0*rstd*n1g[lane]    + n1b[lane];
    g_xn[(size_t)warp*64 + lane+32] = d1*rstd*n1g[lane+32] + n1b[lane+32];
    if (lane < 2) g_posd[(size_t)warp*2 + lane] = pos[((size_t)b*Nv + n)*2 + lane];
}

// ---------------- normalize + 3x3 gaussian reconstruct fused ----------------
__global__ void blur_kernel(){
    int t = blockIdx.x * blockDim.x + threadIdx.x;
    if (t >= Bv*Nv*Cv) return;
    int c = t & 63; int q = t >> 6; int hw = q % Nv; int b = q / Nv;
    int yy = hw / Wv, xx = hw % Wv;
    const float e1 = 0.88249690f, e2 = 0.77880078f;
    const float S  = 1.0f + 4.0f*(e1 + e2);
    const float wt[3] = {1.0f/S, e1/S, e2/S};
    float cc = g_cnt[b*Nv + hw];
    float maskc = cc > 0.f ? 1.f : 0.f;
    float featc = (g_segf[t] / (cc + 1e-6f)) * maskc;
    float bf = 0.f, bm = 0.f;
    #pragma unroll
    for (int dy = -1; dy <= 1; dy++){
        #pragma unroll
        for (int dx = -1; dx <= 1; dx++){
            int y2 = yy + dy, x2 = xx + dx;
            if (y2 >= 0 && y2 < Wv && x2 >= 0 && x2 < Wv){
                int hw2 = y2*Wv + x2;
                float cn = g_cnt[b*Nv + hw2];
                float mn = cn > 0.f ? 1.f : 0.f;
                float fn = (g_segf[((size_t)b*Nv + hw2)*64 + c] / (cn + 1e-6f)) * mn;
                float w = wt[dy*dy + dx*dx];
                bf += w * fn; bm += w * mn;
            }
        }
    }
    float fi = bf / (bm + 1e-6f);
    fi = (bm > 0.f) ? fi : 0.f;
    g_fmap[t] = featc + (1.f - maskc) * fi;
}

// ---------------- sr 4x4 stride-4 conv as tiled GEMM ------------------------
__global__ void srconv_kernel(const float* __restrict__ srw, const float* __restrict__ srb){
    __shared__ float As[16][64];
    __shared__ float Bs[16][64];
    int m0 = blockIdx.x * 64;
    int tid = threadIdx.x, tx = tid & 15, ty = tid >> 4;
    float acc[4][4] = {};
    for (int k0 = 0; k0 < 1024; k0 += 16){
        #pragma unroll
        for (int i = 0; i < 4; i++){
            int e = tid + i*256;
            int kk = e & 15, mm = e >> 4;
            int m = m0 + mm, k = k0 + kk;
            int b = m / NSR, s2 = m % NSR;
            int oy = s2 / 14, ox = s2 % 14;
            int kyx = k >> 6, ci = k & 63;
            int ky = kyx >> 2, kx = kyx & 3;
            As[kk][mm] = g_fmap[(((size_t)b*Nv) + (oy*4+ky)*Wv + (ox*4+kx))*64 + ci];
        }
        #pragma unroll
        for (int i = 0; i < 4; i++){
            int e = tid + i*256;
            int n = e & 63, kk = e >> 6;
            int k = k0 + kk;
            int kyx = k >> 6, ci = k & 63;
            Bs[kk][n] = srw[(size_t)n*1024 + ci*16 + kyx];
        }
        __syncthreads();
        #pragma unroll
        for (int kk = 0; kk < 16; kk++){
            float a[4], bb[4];
            #pragma unroll
            for (int i = 0; i < 4; i++) a[i] = As[kk][ty*4+i];
            #pragma unroll
            for (int j = 0; j < 4; j++) bb[j] = Bs[kk][tx*4+j];
            #pragma unroll
            for (int i = 0; i < 4; i++)
                #pragma unroll
                for (int j = 0; j < 4; j++) acc[i][j] += a[i]*bb[j];
        }
        __syncthreads();
    }
    #pragma unroll
    for (int i = 0; i < 4; i++)
        #pragma unroll
        for (int j = 0; j < 4; j++){
            int m = m0 + ty*4 + i, n = tx*4 + j;
            g_xs[(size_t)m*64 + n] = acc[i][j] + srb[n];
        }
}

// ---------------- generic LN kernels ----------------------------------------
__global__ void ln64_kernel(const float* __restrict__ in, float* __restrict__ outb,
                            const float* __restrict__ g, const float* __restrict__ b, int rows){
    int warp = (blockIdx.x * blockDim.x + threadIdx.x) >> 5;
    int lane = threadIdx.x & 31;
    if (warp >= rows) return;
    const float* xr = in + (size_t)warp*64;
    float v0 = xr[lane], v1 = xr[lane+32];
    float m = warp_sum(v0+v1) * (1.0f/64.0f);
    float d0 = v0-m, d1 = v1-m;
    float rstd = rsqrtf(warp_sum(d0*d0+d1*d1)*(1.0f/64.0f) + 1e-5f);
    outb[(size_t)warp*64 + lane]    = d0*rstd*g[lane]    + b[lane];
    outb[(size_t)warp*64 + lane+32] = d1*rstd*g[lane+32] + b[lane+32];
}
// ln128 + emit split-bf16 (feeds tensor-core fc1)
__global__ void ln128_split_kernel(const float* __restrict__ in,
                                   __nv_bfloat16* __restrict__ oh, __nv_bfloat16* __restrict__ ol,
                                   const float* __restrict__ g, const float* __restrict__ b, int rows){
    int warp = (blockIdx.x * blockDim.x + threadIdx.x) >> 5;
    int lane = threadIdx.x & 31;
    if (warp >= rows) return;
    const float* xr = in + (size_t)warp*128;
    float v[4]; float s = 0.f;
    #pragma unroll
    for (int r = 0; r < 4; r++){ v[r] = xr[lane + 32*r]; s += v[r]; }
    float m = warp_sum(s) * (1.0f/128.0f);
    float vs = 0.f;
    #pragma unroll
    for (int r = 0; r < 4; r++){ v[r] -= m; vs += v[r]*v[r]; }
    float rstd = rsqrtf(warp_sum(vs)*(1.0f/128.0f) + 1e-5f);
    #pragma unroll
    for (int r = 0; r < 4; r++){
        int d = lane + 32*r;
        float o = v[r]*rstd*g[d] + b[d];
        __nv_bfloat16 h, l; bsplit(o, h, l);
        oh[(size_t)warp*128 + d] = h;
        ol[(size_t)warp*128 + d] = l;
    }
}

// ---------------- weight transpose+split: W[K][N] -> Wt hi/lo [N][K] --------
__global__ void split_w_kernel(const float* __restrict__ W,
                               __nv_bfloat16* __restrict__ Wh, __nv_bfloat16* __restrict__ Wl,
                               int K, int N){
    int t = blockIdx.x * blockDim.x + threadIdx.x;
    if (t >= K*N) return;
    int n = t / K, k = t % K;
    float w = W[(size_t)k*N + n];
    __nv_bfloat16 h, l; bsplit(w, h, l);
    Wh[t] = h; Wl[t] = l;
}

// ---------------- tiled SGEMM v2 (fp32, small-K GEMMs) ----------------------
__global__ void sgemm_kernel(const float* __restrict__ A, const float* __restrict__ Bm,
                             const float* __restrict__ bias, const float* __restrict__ add,
                             float* __restrict__ C, int M, int N, int K, int act){
    __shared__ float As[2][8][64];
    __shared__ float Bs[2][8][128];
    int m0 = blockIdx.y * 64, n0 = blockIdx.x * 128;
    int tid = threadIdx.x;
    int tx = tid & 15, ty = tid >> 4;
    int am = tid >> 1, ak = (tid & 1) * 4;
    int bkk = tid >> 4, bn = (tid & 15) * 8;

    const float* Arow = A + (size_t)(m0 + am) * K;

    float4 ra  = *(const float4*)&Arow[ak];
    float4 rb0 = *(const float4*)&Bm[(size_t)bkk*N + n0 + bn];
    float4 rb1 = *(const float4*)&Bm[(size_t)bkk*N + n0 + bn + 4];
    As[0][ak+0][am] = ra.x; As[0][ak+1][am] = ra.y;
    As[0][ak+2][am] = ra.z; As[0][ak+3][am] = ra.w;
    *(float4*)&Bs[0][bkk][bn]   = rb0;
    *(float4*)&Bs[0][bkk][bn+4] = rb1;
    __syncthreads();

    float acc[8][8] = {};
    int nk = K >> 3;
    for (int kt = 0; kt < nk; kt++){
        int cur = kt & 1, nxt = cur ^ 1;
        if (kt + 1 < nk){
            int k0 = (kt + 1) << 3;
            ra  = *(const float4*)&Arow[k0 + ak];
            rb0 = *(const float4*)&Bm[(size_t)(k0 + bkk)*N + n0 + bn];
            rb1 = *(const float4*)&Bm[(size_t)(k0 + bkk)*N + n0 + bn + 4];
        }
        #pragma unroll
        for (int kk = 0; kk < 8; kk++){
            float a[8], b[8];
            *(float4*)&a[0] = *(const float4*)&As[cur][kk][ty*8];
            *(float4*)&a[4] = *(const float4*)&As[cur][kk][ty*8 + 4];
            *(float4*)&b[0] = *(const float4*)&Bs[cur][kk][tx*8];
            *(float4*)&b[4] = *(const float4*)&Bs[cur][kk][tx*8 + 4];
            #pragma unroll
            for (int i = 0; i < 8; i++)
                #pragma unroll
                for (int j = 0; j < 8; j++) acc[i][j] += a[i]*b[j];
        }
        if (kt + 1 < nk){
            As[nxt][ak+0][am] = ra.x; As[nxt][ak+1][am] = ra.y;
            As[nxt][ak+2][am] = ra.z; As[nxt][ak+3][am] = ra.w;
            *(float4*)&Bs[nxt][bkk][bn]   = rb0;
            *(float4*)&Bs[nxt][bkk][bn+4] = rb1;
            __syncthreads();
        }
    }
    #pragma unroll
    for (int i = 0; i < 8; i++){
        int m = m0 + ty*8 + i;
        #pragma unroll
        for (int j = 0; j < 8; j++){
            int n = n0 + tx*8 + j;
            float v = acc[i][j];
            if (bias) v += bias[n];
            if (add)  v += add[(size_t)m*N + n];
            if (act == 1) v = 0.5f * v * (1.0f + erff(v * 0.70710678118654752f));
            C[(size_t)m*N + n] = v;
        }
    }
}

// ---------------- bf16x3 tensor-core GEMM (mma.sync m16n8k16) ---------------
// Block 64(M) x 128(N), 128 threads (4 warps, 2x2), warp tile 32x64.
// A: [M][K] bf16 hi/lo row-major; Bt: [N][K] bf16 hi/lo (k-contiguous).
// MODE 0: C = A@B + bias + add (f32 out).  MODE 1: gelu(A@B+bias) -> split bf16.
__device__ __forceinline__ void mma16816(float* c, const uint32* a, const uint32* b){
    asm volatile("mma.sync.aligned.m16n8k16.row.col.f32.bf16.bf16.f32 "
        "{%0,%1,%2,%3}, {%4,%5,%6,%7}, {%8,%9}, {%0,%1,%2,%3};"
        : "+f"(c[0]), "+f"(c[1]), "+f"(c[2]), "+f"(c[3])
        : "r"(a[0]), "r"(a[1]), "r"(a[2]), "r"(a[3]), "r"(b[0]), "r"(b[1]));
}

template<int MODE>
__global__ void mma_gemm_kernel(const __nv_bfloat16* __restrict__ Ah, const __nv_bfloat16* __restrict__ Al,
                                const __nv_bfloat16* __restrict__ Bth, const __nv_bfloat16* __restrict__ Btl,
                                const float* __restrict__ bias, const float* __restrict__ add,
                                float* __restrict__ C,
                                __nv_bfloat16* __restrict__ Oh, __nv_bfloat16* __restrict__ Ol,
                                int M, int N, int K){
    __shared__ uint32 AsH[2][64][9], AsL[2][64][9];
    __shared__ uint32 BsH[2][128][9], BsL[2][128][9];
    int tid = threadIdx.x, lane = tid & 31, wid = tid >> 5;
    int g = lane >> 2, t4 = lane & 3;
    int warp_m = wid >> 1, warp_n = wid & 1;
    int m0 = blockIdx.y * 64, n0 = blockIdx.x * 128;
    int K2 = K >> 1;

    // loader indices
    int ar[4], ac[4], br[8], bc[8];
    #pragma unroll
    for (int i = 0; i < 4; i++){ int w = tid + i*128; ar[i] = w >> 3; ac[i] = w & 7; }
    #pragma unroll
    for (int i = 0; i < 8; i++){ int w = tid + i*128; br[i] = w >> 3; bc[i] = w & 7; }

    uint32 pah[4], pal[4], pbh[8], pbl[8];
    #pragma unroll
    for (int i = 0; i < 4; i++){
        size_t rowoff = (size_t)(m0 + ar[i]) * K2;
        pah[i] = ((const uint32*)Ah)[rowoff + ac[i]];
        pal[i] = ((const uint32*)Al)[rowoff + ac[i]];
    }
    #pragma unroll
    for (int i = 0; i < 8; i++){
        size_t rowoff = (size_t)(n0 + br[i]) * K2;
        pbh[i] = ((const uint32*)Bth)[rowoff + bc[i]];
        pbl[i] = ((const uint32*)Btl)[rowoff + bc[i]];
    }
    #pragma unroll
    for (int i = 0; i < 4; i++){ AsH[0][ar[i]][ac[i]] = pah[i]; AsL[0][ar[i]][ac[i]] = pal[i]; }
    #pragma unroll
    for (int i = 0; i < 8; i++){ BsH[0][br[i]][bc[i]] = pbh[i]; BsL[0][br[i]][bc[i]] = pbl[i]; }
    __syncthreads();

    float acc[2][8][4];
    #pragma unroll
    for (int fm = 0; fm < 2; fm++)
        #pragma unroll
        for (int fn = 0; fn < 8; fn++)
            #pragma unroll
            for (int i = 0; i < 4; i++) acc[fm][fn][i] = 0.f;

    int nk = K >> 4;
    for (int kt = 0; kt < nk; kt++){
        int cur = kt & 1, nxt = cur ^ 1;
        if (kt + 1 < nk){
            int kw = (kt + 1) * 8;
            #pragma unroll
            for (int i = 0; i < 4; i++){
                size_t rowoff = (size_t)(m0 + ar[i]) * K2 + kw;
                pah[i] = ((const uint32*)Ah)[rowoff + ac[i]];
                pal[i] = ((const uint32*)Al)[rowoff + ac[i]];
            }
            #pragma unroll
            for (int i = 0; i < 8; i++){
                size_t rowoff = (size_t)(n0 + br[i]) * K2 + kw;
                pbh[i] = ((const uint32*)Bth)[rowoff + bc[i]];
                pbl[i] = ((const uint32*)Btl)[rowoff + bc[i]];
            }
        }
        // fragment loads
        uint32 ah[2][4], al[2][4], bh[8][2], bl[8][2];
        #pragma unroll
        for (int fm = 0; fm < 2; fm++){
            int r0 = warp_m*32 + fm*16 + g;
            ah[fm][0] = AsH[cur][r0][t4];     ah[fm][1] = AsH[cur][r0+8][t4];
            ah[fm][2] = AsH[cur][r0][t4+4];   ah[fm][3] = AsH[cur][r0+8][t4+4];
            al[fm][0] = AsL[cur][r0][t4];     al[fm][1] = AsL[cur][r0+8][t4];
            al[fm][2] = AsL[cur][r0][t4+4];   al[fm][3] = AsL[cur][r0+8][t4+4];
        }
        #pragma unroll
        for (int fn = 0; fn < 8; fn++){
            int r0 = warp_n*64 + fn*8 + g;
            bh[fn][0] = BsH[cur][r0][t4]; bh[fn][1] = BsH[cur][r0][t4+4];
            bl[fn][0] = BsL[cur][r0][t4]; bl[fn][1] = BsL[cur][r0][t4+4];
        }
        #pragma unroll
        for (int fn = 0; fn < 8; fn++)
            #pragma unroll
            for (int fm = 0; fm < 2; fm++){
                mma16816(acc[fm][fn], ah[fm], bh[fn]);
                mma16816(acc[fm][fn], ah[fm], bl[fn]);
                mma16816(acc[fm][fn], al[fm], bh[fn]);
            }
        if (kt + 1 < nk){
            #pragma unroll
            for (int i = 0; i < 4; i++){ AsH[nxt][ar[i]][ac[i]] = pah[i]; AsL[nxt][ar[i]][ac[i]] = pal[i]; }
            #pragma unroll
            for (int i = 0; i < 8; i++){ BsH[nxt][br[i]][bc[i]] = pbh[i]; BsL[nxt][br[i]][bc[i]] = pbl[i]; }
            __syncthreads();
        }
    }

    // epilogue
    #pragma unroll
    for (int fm = 0; fm < 2; fm++){
        int m1 = m0 + warp_m*32 + fm*16 + g;
        int m2 = m1 + 8;
        #pragma unroll
        for (int fn = 0; fn < 8; fn++){
            int n = n0 + warp_n*64 + fn*8 + t4*2;
            float c0 = acc[fm][fn][0] + bias[n];
            float c1 = acc[fm][fn][1] + bias[n+1];
            float c2 = acc[fm][fn][2] + bias[n];
            float c3 = acc[fm][fn][3] + bias[n+1];
            if (MODE == 0){
                c0 += add[(size_t)m1*N + n];   c1 += add[(size_t)m1*N + n + 1];
                c2 += add[(size_t)m2*N + n];   c3 += add[(size_t)m2*N + n + 1];
                *(float2*)&C[(size_t)m1*N + n] = make_float2(c0, c1);
                *(float2*)&C[(size_t)m2*N + n] = make_float2(c2, c3);
            } else {
                c0 = 0.5f*c0*(1.0f + erff(c0*0.70710678118654752f));
                c1 = 0.5f*c1*(1.0f + erff(c1*0.70710678118654752f));
                c2 = 0.5f*c2*(1.0f + erff(c2*0.70710678118654752f));
                c3 = 0.5f*c3*(1.0f + erff(c3*0.70710678118654752f));
                __nv_bfloat16 h0,l0,h1,l1,h2,l2,h3,l3;
                bsplit(c0,h0,l0); bsplit(c1,h1,l1); bsplit(c2,h2,l2); bsplit(c3,h3,l3);
                __nv_bfloat162 hp1; hp1.x = h0; hp1.y = h1;
                __nv_bfloat162 lp1; lp1.x = l0; lp1.y = l1;
                __nv_bfloat162 hp2; hp2.x = h2; hp2.y = h3;
                __nv_bfloat162 lp2; lp2.x = l2; lp2.y = l3;
                *(__nv_bfloat162*)&Oh[(size_t)m1*N + n] = hp1;
                *(__nv_bfloat162*)&Ol[(size_t)m1*N + n] = lp1;
                *(__nv_bfloat162*)&Oh[(size_t)m2*N + n] = hp2;
                *(__nv_bfloat162*)&Ol[(size_t)m2*N + n] = lp2;
            }
        }
    }
}

// ---------------- fused cross-attention -------------------------------------
#define QPW 8
#define JPAD 224
__global__ void attn_kernel(){
    extern __shared__ float sm[];
    float* Ks = sm;
    float* Vs = Ks + JPAD*65;
    float* Qs = Vs + JPAD*64;
    float* Pp = Qs + 8*QPW*64;
    int bh = blockIdx.y;
    int b = bh >> 1, h = bh & 1;
    int tid = threadIdx.x, lane = tid & 31, w = tid >> 5;
    for (int e = tid; e < JPAD*64; e += 256){
        int j = e >> 6, d = e & 63;
        float kv = 0.f, vv = 0.f;
        if (j < NSR){
            size_t base = ((size_t)b*NSR + j)*128 + h*64 + d;
            kv = g_kb[base]; vv = g_vb[base];
        }
        Ks[j*65 + d] = kv;
        Vs[e] = vv;
    }
    int qbase = blockIdx.x * 64 + w * QPW;
    for (int e = lane; e < QPW*64; e += 32){
        int qi = e >> 6, d = e & 63;
        int gq = qbase + qi;
        Qs[(w*QPW + qi)*64 + d] = (gq < ND) ? g_q[((size_t)b*ND + gq)*128 + h*64 + d] : 0.f;
    }
    __syncthreads();

    float acc[QPW][7];
    #pragma unroll
    for (int qi = 0; qi < QPW; qi++)
        #pragma unroll
        for (int t = 0; t < 7; t++) acc[qi][t] = 0.f;

    for (int d = 0; d < 64; d++){
        float qv[QPW];
        #pragma unroll
        for (int qi = 0; qi < QPW; qi++) qv[qi] = Qs[(w*QPW + qi)*64 + d];
        #pragma unroll
        for (int t = 0; t < 7; t++){
            float kv = Ks[(lane + 32*t)*65 + d];
            #pragma unroll
            for (int qi = 0; qi < QPW; qi++) acc[qi][t] += qv[qi]*kv;
        }
    }
    const float scale = 0.17677669529663687f;
    float sums[QPW];
    #pragma unroll
    for (int qi = 0; qi < QPW; qi++){
        float mx = -1e30f;
        #pragma unroll
        for (int t = 0; t < 7; t++){
            int j = lane + 32*t;
            acc[qi][t] *= scale;
            if (j < NSR) mx = fmaxf(mx, acc[qi][t]);
        }
        mx = warp_max(mx);
        float s = 0.f;
        #pragma unroll
        for (int t = 0; t < 7; t++){
            int j = lane + 32*t;
            if (j < NSR){
                float e = expf(acc[qi][t] - mx);
                Pp[(w*QPW + qi)*196 + j] = e;
                s += e;
            }
        }
        sums[qi] = warp_sum(s);
    }
    __syncwarp();
    float o0[QPW] = {}, o1[QPW] = {};
    for (int j = 0; j < NSR; j++){
        float v0 = Vs[j*64 + lane], v1 = Vs[j*64 + lane + 32];
        #pragma unroll
        for (int qi = 0; qi < QPW; qi++){
            float p = Pp[(w*QPW + qi)*196 + j];
            o0[qi] += p*v0; o1[qi] += p*v1;
        }
    }
    #pragma unroll
    for (int qi = 0; qi < QPW; qi++){
        int gq = qbase + qi;
        if (gq < ND){
            size_t base = ((size_t)b*ND + gq)*128 + h*64;
            float inv = 1.0f / sums[qi];
            g_oatt[base + lane]      = o0[qi]*inv;
            g_oatt[base + lane + 32] = o1[qi]*inv;
        }
    }
}

// ---------------- bilinear grid-sample of pos_embed, add into out -----------
__global__ void possample_kernel(const float* __restrict__ pe, float* __restrict__ out){
    int warp = (blockIdx.x * blockDim.x + threadIdx.x) >> 5;
    int lane = threadIdx.x & 31;
    if (warp >= Bv*ND) return;
    float px = g_posd[(size_t)warp*2], py = g_posd[(size_t)warp*2 + 1];
    float gx = px*2.f - 1.f, gy = py*2.f - 1.f;
    float ix = ((gx + 1.f)*56.f - 1.f)*0.5f;
    float iy = ((gy + 1.f)*56.f - 1.f)*0.5f;
    float x0 = floorf(ix), y0 = floorf(iy);
    float wx = ix - x0,   wy = iy - y0;
    float accv[4] = {};
    #pragma unroll
    for (int cy = 0; cy < 2; cy++){
        #pragma unroll
        for (int cx = 0; cx < 2; cx++){
            float xc = x0 + cx, yc = y0 + cy;
            float wgt = (cx ? wx : 1.f-wx) * (cy ? wy : 1.f-wy);
            bool valid = (xc >= 0.f) && (xc < 56.f) && (yc >= 0.f) && (yc < 56.f);
            float wv = valid ? wgt : 0.f;
            int xi = (int)fminf(fmaxf(xc, 0.f), 55.f);
            int yi = (int)fminf(fmaxf(yc, 0.f), 55.f);
            int lin = yi*56 + xi;
            #pragma unroll
            for (int r = 0; r < 4; r++)
                accv[r] += pe[(size_t)lin*128 + lane + 32*r] * wv;
        }
    }
    #pragma unroll
    for (int r = 0; r < 4; r++)
        out[(size_t)warp*128 + lane + 32*r] += accv[r];
}

// ---------------- launcher ---------------------------------------------------
extern "C" void kernel_launch(void* const* d_in, const int* in_sizes, int n_in,
                              void* d_out, int out_size){
    const float* x        = (const float*)d_in[0];
    const float* pos      = (const float*)d_in[1];
    const float* pos_embed= (const float*)d_in[2];
    const float* noise_u  = (const float*)d_in[3];
    const float* norm_g   = (const float*)d_in[4];
    const float* norm_b   = (const float*)d_in[5];
    const float* conf_w   = (const float*)d_in[6];
    const float* conf_b   = (const float*)d_in[7];
    const float* n1g      = (const float*)d_in[8];
    const float* n1b      = (const float*)d_in[9];
    const float* q_w      = (const float*)d_in[10];
    const float* k_w      = (const float*)d_in[11];
    const float* v_w      = (const float*)d_in[12];
    const float* proj_w   = (const float*)d_in[13];
    const float* proj_b   = (const float*)d_in[14];
    const float* sr_w     = (const float*)d_in[15];
    const float* sr_b     = (const float*)d_in[16];
    const float* srn_g    = (const float*)d_in[17];
    const float* srn_b    = (const float*)d_in[18];
    const float* fc_w     = (const float*)d_in[19];
    const float* fc_b     = (const float*)d_in[20];
    const float* n2g      = (const float*)d_in[21];
    const float* n2b      = (const float*)d_in[22];
    const float* fc1_w    = (const float*)d_in[23];
    const float* fc1_b    = (const float*)d_in[24];
    const float* fc2_w    = (const float*)d_in[25];
    const float* fc2_b    = (const float*)d_in[26];
    float* out = (float*)d_out;

    float *p_xn, *p_xs, *p_q, *p_oatt, *p_tproj, *p_xdown, *p_x2, *p_kb, *p_vb;
    __nv_bfloat16 *p_xn2h, *p_xn2l, *p_hidh, *p_hidl, *p_w1h, *p_w1l, *p_w2h, *p_w2l;
    cudaGetSymbolAddress((void**)&p_xn,    g_xn);
    cudaGetSymbolAddress((void**)&p_xs,    g_xs);
    cudaGetSymbolAddress((void**)&p_q,     g_q);
    cudaGetSymbolAddress((void**)&p_kb,    g_kb);
    cudaGetSymbolAddress((void**)&p_vb,    g_vb);
    cudaGetSymbolAddress((void**)&p_oatt,  g_oatt);
    cudaGetSymbolAddress((void**)&p_tproj, g_tproj);
    cudaGetSymbolAddress((void**)&p_xdown, g_xdown);
    cudaGetSymbolAddress((void**)&p_x2,    g_x2);
    cudaGetSymbolAddress((void**)&p_xn2h,  g_xn2h);
    cudaGetSymbolAddress((void**)&p_xn2l,  g_xn2l);
    cudaGetSymbolAddress((void**)&p_hidh,  g_hidh);
    cudaGetSymbolAddress((void**)&p_hidl,  g_hidl);
    cudaGetSymbolAddress((void**)&p_w1h,   g_w1h);
    cudaGetSymbolAddress((void**)&p_w1l,   g_w1l);
    cudaGetSymbolAddress((void**)&p_w2h,   g_w2h);
    cudaGetSymbolAddress((void**)&p_w2l,   g_w2l);

    zero_kernel<<<4096, 256>>>();
    // weight splits (independent; issue early)
    split_w_kernel<<<(DOUT*HIDN + 255)/256, 256>>>(fc1_w, p_w1h, p_w1l, DOUT, HIDN);
    split_w_kernel<<<(HIDN*DOUT + 255)/256, 256>>>(fc2_w, p_w2h, p_w2l, HIDN, DOUT);

    ln_scatter_kernel<<<(Bv*Nv + 7)/8, 256>>>(x, pos, n1g, n1b);
    score_kernel<<<(Bv*NS + 255)/256, 256>>>(x, noise_u, norm_g, norm_b, conf_w, conf_b);
    topk_kernel<<<Bv, 1024>>>();
    gather_ln_kernel<<<(Bv*ND + 7)/8, 256>>>(x, pos, n1g, n1b);
    blur_kernel<<<(Bv*Nv*Cv + 255)/256, 256>>>();
    srconv_kernel<<<196, 256>>>(sr_w, sr_b);
    ln64_kernel<<<(Bv*NSR + 7)/8, 256>>>(p_xs, p_xs, srn_g, srn_b, Bv*NSR);

    // q = xn @ q_w ; k = xs @ k_w ; v = xs @ v_w   (no bias)
    sgemm_kernel<<<dim3(1, (Bv*ND)/64), 128>>>(p_xn, q_w, nullptr, nullptr, p_q, Bv*ND, 128, 64, 0);
    sgemm_kernel<<<dim3(1, (Bv*NSR)/64), 128>>>(p_xs, k_w, nullptr, nullptr, p_kb, Bv*NSR, 128, 64, 0);
    sgemm_kernel<<<dim3(1, (Bv*NSR)/64), 128>>>(p_xs, v_w, nullptr, nullptr, p_vb, Bv*NSR, 128, 64, 0);

    // fused attention
    size_t attn_smem = (size_t)(JPAD*65 + JPAD*64 + 8*QPW*64 + 8*QPW*196) * sizeof(float);
    cudaFuncSetAttribute(attn_kernel, cudaFuncAttributeMaxDynamicSharedMemorySize, (int)attn_smem);
    attn_kernel<<<dim3(14, Bv*2), 256, attn_smem>>>();

    // tproj = oatt @ proj_w + proj_b ; x2 = xdown @ fc_w + fc_b + tproj
    sgemm_kernel<<<dim3(1, (Bv*ND)/64), 128>>>(p_oatt, proj_w, proj_b, nullptr, p_tproj, Bv*ND, 128, 128, 0);
    sgemm_kernel<<<dim3(1, (Bv*ND)/64), 128>>>(p_xdown, fc_w, fc_b, p_tproj, p_x2, Bv*ND, 128, 64, 0);

    // LN2 -> split bf16 xn2
    ln128_split_kernel<<<(Bv*ND + 7)/8, 256>>>(p_x2, p_xn2h, p_xn2l, n2g, n2b, Bv*ND);

    // hid = gelu(xn2 @ fc1 + b1) -> split bf16 (tensor cores)
    mma_gemm_kernel<1><<<dim3(HIDN/128, MROWS/64), 128>>>(
        p_xn2h, p_xn2l, p_w1h, p_w1l, fc1_b, nullptr, nullptr, p_hidh, p_hidl,
        MROWS, HIDN, DOUT);
    // out = x2 + hid @ fc2 + b2 (tensor cores)
    mma_gemm_kernel<0><<<dim3(DOUT/128, MROWS/64), 128>>>(
        p_hidh, p_hidl, p_w2h, p_w2l, fc2_b, p_x2, out, nullptr, nullptr,
        MROWS, DOUT, HIDN);

    // out += grid_sample(pos_embed)
    possample_kernel<<<(Bv*ND + 7)/8, 256>>>(pos_embed, out);
}

// round 12
// speedup vs baseline: 1.5532x; 1.1154x over previous
#include <cuda_runtime.h>
#include <cuda_bf16.h>
#include <math.h>

typedef unsigned int uint32;

// Problem constants (fixed by setup_inputs)
#define Bv 64
#define Nv 3136
#define Cv 64
#define DOUT 128
#define Wv 56
#define NG 49
#define SAMPLE 784
#define ND 833            // NG + SAMPLE
#define NS 3087           // Nv - NG
#define NSR 196           // (56/4)^2
#define HIDN 512
#define MROWS (Bv*ND)     // 53312
#define MSR   (Bv*NSR)    // 12544
#define KCAT  192         // 128 (oatt) + 64 (xdown)

// ---------------- scratch (static device memory; allocation-free) ----------
__device__ float g_scores[Bv*NS];
__device__ int   g_idx  [Bv*SAMPLE];
__device__ float g_posd [Bv*ND*2];
__device__ float g_segf [Bv*Nv*Cv];
__device__ float g_cnt  [Bv*Nv];
__device__ float g_fmap [Bv*Nv*Cv];
__device__ float g_xs   [MSR*Cv];
__device__ float g_q    [MROWS*DOUT];
__device__ float g_kv   [MSR*256];
__device__ float g_x2   [MROWS*DOUT];
// bf16-split operands for tensor-core GEMMs
__device__ __align__(16) __nv_bfloat16 g_xnh[MROWS*Cv];
__device__ __align__(16) __nv_bfloat16 g_xnl[MROWS*Cv];
__device__ __align__(16) __nv_bfloat16 g_xsh[MSR*Cv];
__device__ __align__(16) __nv_bfloat16 g_xsl[MSR*Cv];
__device__ __align__(16) __nv_bfloat16 g_cath[(size_t)MROWS*KCAT];
__device__ __align__(16) __nv_bfloat16 g_catl[(size_t)MROWS*KCAT];
__device__ __align__(16) __nv_bfloat16 g_xn2h[MROWS*DOUT];
__device__ __align__(16) __nv_bfloat16 g_xn2l[MROWS*DOUT];
__device__ __align__(16) __nv_bfloat16 g_hidh[(size_t)MROWS*HIDN];
__device__ __align__(16) __nv_bfloat16 g_hidl[(size_t)MROWS*HIDN];
__device__ __align__(16) __nv_bfloat16 g_w1h[HIDN*DOUT];   // [n][k]
__device__ __align__(16) __nv_bfloat16 g_w1l[HIDN*DOUT];
__device__ __align__(16) __nv_bfloat16 g_w2h[DOUT*HIDN];
__device__ __align__(16) __nv_bfloat16 g_w2l[DOUT*HIDN];
__device__ __align__(16) __nv_bfloat16 g_wqh[DOUT*Cv];
__device__ __align__(16) __nv_bfloat16 g_wql[DOUT*Cv];
__device__ __align__(16) __nv_bfloat16 g_wkvh[256*Cv];
__device__ __align__(16) __nv_bfloat16 g_wkvl[256*Cv];
__device__ __align__(16) __nv_bfloat16 g_wpfh[DOUT*KCAT];
__device__ __align__(16) __nv_bfloat16 g_wpfl[DOUT*KCAT];
__device__ float g_biaspf[DOUT];

__device__ __forceinline__ float warp_sum(float v){
    #pragma unroll
    for (int o = 16; o; o >>= 1) v = __fadd_rn(v, __shfl_xor_sync(0xffffffffu, v, o));
    return v;
}
__device__ __forceinline__ float warp_max(float v){
    #pragma unroll
    for (int o = 16; o; o >>= 1) v = fmaxf(v, __shfl_xor_sync(0xffffffffu, v, o));
    return v;
}
__device__ __forceinline__ void bsplit(float v, __nv_bfloat16& h, __nv_bfloat16& l){
    h = __float2bfloat16(v);
    l = __float2bfloat16(v - __bfloat162float(h));
}

// ---------------- zero segf/cnt -------------------------------------------
__global__ void zero_kernel(){
    int stride = gridDim.x * blockDim.x;
    int t = blockIdx.x * blockDim.x + threadIdx.x;
    for (int i = t; i < Bv*Nv*Cv; i += stride) g_segf[i] = 0.f;
    for (int i = t; i < Bv*Nv;    i += stride) g_cnt[i]  = 0.f;
}

// ---------------- LN(x) -> scatter directly (token2map segment_sum) --------
__global__ void ln_scatter_kernel(const float* __restrict__ x, const float* __restrict__ pos,
                                  const float* __restrict__ n1g, const float* __restrict__ n1b){
    int warp = (blockIdx.x * blockDim.x + threadIdx.x) >> 5;
    int lane = threadIdx.x & 31;
    if (warp >= Bv*Nv) return;
    const float* xr = x + (size_t)warp * Cv;
    float v0 = xr[lane], v1 = xr[lane+32];
    float m = warp_sum(v0 + v1) * (1.0f/64.0f);
    float d0 = v0 - m, d1 = v1 - m;
    float var = warp_sum(d0*d0 + d1*d1) * (1.0f/64.0f);
    float rstd = rsqrtf(var + 1e-5f);
    float xsn0 = d0*rstd*n1g[lane]    + n1b[lane];
    float xsn1 = d1*rstd*n1g[lane+32] + n1b[lane+32];
    int b = warp / Nv;
    int p = 0;
    if (lane == 0){
        float px = fminf(fmaxf(pos[(size_t)warp*2],   0.f), 1.f) * 55.f;
        float py = fminf(fmaxf(pos[(size_t)warp*2+1], 0.f), 1.f) * 55.f;
        p = (int)rintf(px) + (int)rintf(py) * Wv;     // half-to-even like jnp.round
    }
    p = __shfl_sync(0xffffffffu, p, 0);
    size_t base = ((size_t)b*Nv + p)*64;
    atomicAdd(&g_segf[base + lane],      xsn0);
    atomicAdd(&g_segf[base + lane + 32], xsn1);
    if (lane == 0) atomicAdd(&g_cnt[b*Nv + p], 1.0f);
}

// ---------------- score path: XLA-CPU semantics -----------------------------
__global__ void score_kernel(const float* __restrict__ x,
                             const float* __restrict__ noise_u,
                             const float* __restrict__ ng, const float* __restrict__ nb,
                             const float* __restrict__ cw, const float* __restrict__ cb){
    int t = blockIdx.x * blockDim.x + threadIdx.x;
    if (t >= Bv*NS) return;
    int b = t / NS, i = t % NS;
    int n = NG + i;
    const float* xr = x + ((size_t)b*Nv + n) * Cv;
    float s = 0.f;
    for (int k = 0; k < 64; k++) s = __fadd_rn(s, xr[k]);
    float m = __fdiv_rn(s, 64.0f);
    float vs = 0.f;
    for (int k = 0; k < 64; k++){
        float d = __fsub_rn(xr[k], m);
        vs = __fadd_rn(vs, __fmul_rn(d, d));
    }
    float var = __fdiv_rn(vs, 64.0f);
    float rstd = __fdiv_rn(1.0f, sqrtf(__fadd_rn(var, 1e-5f)));   // CPU rsqrt = 1/sqrt
    float c = 0.f;
    for (int k = 0; k < 64; k++){
        float h = __fmul_rn(__fsub_rn(xr[k], m), rstd);
        float tt = __fadd_rn(__fmul_rn(h, ng[k]), nb[k]);
        c = __fadd_rn(c, __fmul_rn(tt, cw[k]));
    }
    float u = noise_u[t];
    float a1 = __fadd_rn(u, 1e-6f);
    float l1 = (float)log((double)a1);
    float inner = __fadd_rn(-l1, 1e-6f);
    float l2 = (float)log((double)inner);
    float noise = -l2;
    g_scores[t] = __fadd_rn(__fadd_rn(c, cb[0]), noise);
}

// ---------------- exact jax top-k: bitonic sort of (score desc, idx asc) ---
__global__ void topk_kernel(){
    __shared__ unsigned long long keys[4096];
    int b = blockIdx.x, tid = threadIdx.x;
    for (int i = tid; i < 4096; i += 1024){
        unsigned long long kk = ~0ULL;
        if (i < NS){
            unsigned u = __float_as_uint(g_scores[(size_t)b*NS + i]);
            u = (u & 0x80000000u) ? ~u : (u | 0x80000000u);
            kk = ((unsigned long long)(~u) << 32) | (unsigned)i;
        }
        keys[i] = kk;
    }
    __syncthreads();
    for (int k = 2; k <= 4096; k <<= 1)
        for (int j = k >> 1; j > 0; j >>= 1){
            for (int t = tid; t < 4096; t += 1024){
                int ixj = t ^ j;
                if (ixj > t){
                    bool up = ((t & k) == 0);
                    unsigned long long a = keys[t], c = keys[ixj];
                    if ((a > c) == up){ keys[t] = c; keys[ixj] = a; }
                }
            }
            __syncthreads();
        }
    for (int i = tid; i < SAMPLE; i += 1024)
        g_idx[b*SAMPLE + i] = (int)(unsigned)(keys[i] & 0xFFFFFFFFULL);
}

// ---- gather: xdown split -> cat cols [128:192), xn split, pos_down --------
__global__ void gather_ln_kernel(const float* __restrict__ x, const float* __restrict__ pos,
                                 const float* __restrict__ n1g, const float* __restrict__ n1b){
    int warp = (blockIdx.x * blockDim.x + threadIdx.x) >> 5;
    int lane = threadIdx.x & 31;
    if (warp >= Bv*ND) return;
    int b = warp / ND, j = warp % ND;
    int n = (j < NG) ? j : (NG + g_idx[b*SAMPLE + (j - NG)]);
    const float* xr = x + ((size_t)b*Nv + n) * Cv;
    float v0 = xr[lane], v1 = xr[lane+32];
    // xdown split into concat buffer cols 128..191
    {
        __nv_bfloat16 h, l;
        size_t cb = (size_t)warp*KCAT + 128;
        bsplit(v0, h, l); g_cath[cb + lane]      = h; g_catl[cb + lane]      = l;
        bsplit(v1, h, l); g_cath[cb + lane + 32] = h; g_catl[cb + lane + 32] = l;
    }
    float m = warp_sum(v0 + v1) * (1.0f/64.0f);
    float d0 = v0 - m, d1 = v1 - m;
    float var = warp_sum(d0*d0 + d1*d1) * (1.0f/64.0f);
    float rstd = rsqrtf(var + 1e-5f);
    float xn0 = d0*rstd*n1g[lane]    + n1b[lane];
    float xn1 = d1*rstd*n1g[lane+32] + n1b[lane+32];
    {
        __nv_bfloat16 h, l;
        bsplit(xn0, h, l); g_xnh[(size_t)warp*64 + lane]      = h; g_xnl[(size_t)warp*64 + lane]      = l;
        bsplit(xn1, h, l); g_xnh[(size_t)warp*64 + lane + 32] = h; g_xnl[(size_t)warp*64 + lane + 32] = l;
    }
    if (lane < 2) g_posd[(size_t)warp*2 + lane] = pos[((size_t)b*Nv + n)*2 + lane];
}

// ---------------- normalize + 3x3 gaussian reconstruct fused ----------------
__global__ void blur_kernel(){
    int t = blockIdx.x * blockDim.x + threadIdx.x;
    if (t >= Bv*Nv*Cv) return;
    int c = t & 63; int q = t >> 6; int hw = q % Nv; int b = q / Nv;
    int yy = hw / Wv, xx = hw % Wv;
    const float e1 = 0.88249690f, e2 = 0.77880078f;
    const float S  = 1.0f + 4.0f*(e1 + e2);
    const float wt[3] = {1.0f/S, e1/S, e2/S};
    float cc = g_cnt[b*Nv + hw];
    float maskc = cc > 0.f ? 1.f : 0.f;
    float featc = (g_segf[t] / (cc + 1e-6f)) * maskc;
    float bf = 0.f, bm = 0.f;
    #pragma unroll
    for (int dy = -1; dy <= 1; dy++){
        #pragma unroll
        for (int dx = -1; dx <= 1; dx++){
            int y2 = yy + dy, x2 = xx + dx;
            if (y2 >= 0 && y2 < Wv && x2 >= 0 && x2 < Wv){
                int hw2 = y2*Wv + x2;
                float cn = g_cnt[b*Nv + hw2];
                float mn = cn > 0.f ? 1.f : 0.f;
                float fn = (g_segf[((size_t)b*Nv + hw2)*64 + c] / (cn + 1e-6f)) * mn;
                float w = wt[dy*dy + dx*dx];
                bf += w * fn; bm += w * mn;
            }
        }
    }
    float fi = bf / (bm + 1e-6f);
    fi = (bm > 0.f) ? fi : 0.f;
    g_fmap[t] = featc + (1.f - maskc) * fi;
}

// ---------------- sr 4x4 stride-4 conv as tiled GEMM (fp32) -----------------
__global__ void srconv_kernel(const float* __restrict__ srw, const float* __restrict__ srb){
    __shared__ float As[16][64];
    __shared__ float Bs[16][64];
    int m0 = blockIdx.x * 64;
    int tid = threadIdx.x, tx = tid & 15, ty = tid >> 4;
    float acc[4][4] = {};
    for (int k0 = 0; k0 < 1024; k0 += 16){
        #pragma unroll
        for (int i = 0; i < 4; i++){
            int e = tid + i*256;
            int kk = e & 15, mm = e >> 4;
            int m = m0 + mm, k = k0 + kk;
            int b = m / NSR, s2 = m % NSR;
            int oy = s2 / 14, ox = s2 % 14;
            int kyx = k >> 6, ci = k & 63;
            int ky = kyx >> 2, kx = kyx & 3;
            As[kk][mm] = g_fmap[(((size_t)b*Nv) + (oy*4+ky)*Wv + (ox*4+kx))*64 + ci];
        }
        #pragma unroll
        for (int i = 0; i < 4; i++){
            int e = tid + i*256;
            int n = e & 63, kk = e >> 6;
            int k = k0 + kk;
            int kyx = k >> 6, ci = k & 63;
            Bs[kk][n] = srw[(size_t)n*1024 + ci*16 + kyx];
        }
        __syncthreads();
        #pragma unroll
        for (int kk = 0; kk < 16; kk++){
            float a[4], bb[4];
            #pragma unroll
            for (int i = 0; i < 4; i++) a[i] = As[kk][ty*4+i];
            #pragma unroll
            for (int j = 0; j < 4; j++) bb[j] = Bs[kk][tx*4+j];
            #pragma unroll
            for (int i = 0; i < 4; i++)
                #pragma unroll
                for (int j = 0; j < 4; j++) acc[i][j] += a[i]*bb[j];
        }
        __syncthreads();
    }
    #pragma unroll
    for (int i = 0; i < 4; i++)
        #pragma unroll
        for (int j = 0; j < 4; j++){
            int m = m0 + ty*4 + i, n = tx*4 + j;
            g_xs[(size_t)m*64 + n] = acc[i][j] + srb[n];
        }
}

// ---------------- ln64 -> split bf16 (feeds k/v mma) ------------------------
__global__ void ln64_split_kernel(const float* __restrict__ in,
                                  __nv_bfloat16* __restrict__ oh, __nv_bfloat16* __restrict__ ol,
                                  const float* __restrict__ g, const float* __restrict__ b, int rows){
    int warp = (blockIdx.x * blockDim.x + threadIdx.x) >> 5;
    int lane = threadIdx.x & 31;
    if (warp >= rows) return;
    const float* xr = in + (size_t)warp*64;
    float v0 = xr[lane], v1 = xr[lane+32];
    float m = warp_sum(v0+v1) * (1.0f/64.0f);
    float d0 = v0-m, d1 = v1-m;
    float rstd = rsqrtf(warp_sum(d0*d0+d1*d1)*(1.0f/64.0f) + 1e-5f);
    float o0 = d0*rstd*g[lane]    + b[lane];
    float o1 = d1*rstd*g[lane+32] + b[lane+32];
    __nv_bfloat16 h, l;
    bsplit(o0, h, l); oh[(size_t)warp*64 + lane]      = h; ol[(size_t)warp*64 + lane]      = l;
    bsplit(o1, h, l); oh[(size_t)warp*64 + lane + 32] = h; ol[(size_t)warp*64 + lane + 32] = l;
}

// ---------------- ln128 -> split bf16 (feeds fc1 mma) -----------------------
__global__ void ln128_split_kernel(const float* __restrict__ in,
                                   __nv_bfloat16* __restrict__ oh, __nv_bfloat16* __restrict__ ol,
                                   const float* __restrict__ g, const float* __restrict__ b, int rows){
    int warp = (blockIdx.x * blockDim.x + threadIdx.x) >> 5;
    int lane = threadIdx.x & 31;
    if (warp >= rows) return;
    const float* xr = in + (size_t)warp*128;
    float v[4]; float s = 0.f;
    #pragma unroll
    for (int r = 0; r < 4; r++){ v[r] = xr[lane + 32*r]; s += v[r]; }
    float m = warp_sum(s) * (1.0f/128.0f);
    float vs = 0.f;
    #pragma unroll
    for (int r = 0; r < 4; r++){ v[r] -= m; vs += v[r]*v[r]; }
    float rstd = rsqrtf(warp_sum(vs)*(1.0f/128.0f) + 1e-5f);
    #pragma unroll
    for (int r = 0; r < 4; r++){
        int d = lane + 32*r;
        float o = v[r]*rstd*g[d] + b[d];
        __nv_bfloat16 h, l; bsplit(o, h, l);
        oh[(size_t)warp*128 + d] = h;
        ol[(size_t)warp*128 + d] = l;
    }
}

// -------- weight transpose+split: W[K][N] -> out[n*ld + kof + k] hi/lo ------
__global__ void split_w_kernel(const float* __restrict__ W,
                               __nv_bfloat16* __restrict__ Wh, __nv_bfloat16* __restrict__ Wl,
                               int K, int N, int ld, int kof){
    int t = blockIdx.x * blockDim.x + threadIdx.x;
    if (t >= K*N) return;
    int n = t / K, k = t % K;
    float w = W[(size_t)k*N + n];
    __nv_bfloat16 h, l; bsplit(w, h, l);
    Wh[(size_t)n*ld + kof + k] = h; Wl[(size_t)n*ld + kof + k] = l;
}
__global__ void biaspf_kernel(const float* __restrict__ pb, const float* __restrict__ fb){
    int t = threadIdx.x;
    if (t < DOUT) g_biaspf[t] = pb[t] + fb[t];
}

// ---------------- bf16x3 tensor-core GEMM (mma.sync m16n8k16) ---------------
// Block 64(M) x 128(N), 128 threads (4 warps 2x2), warp tile 32x64.
// A: [M][K] hi/lo row-major; Bt: [N][K] hi/lo (k-contiguous). K%16==0.
// MODE 0: C = A@B (+bias)(+add) f32.  MODE 1: gelu(A@B+bias) -> split bf16.
__device__ __forceinline__ void mma16816(float* c, const uint32* a, const uint32* b){
    asm volatile("mma.sync.aligned.m16n8k16.row.col.f32.bf16.bf16.f32 "
        "{%0,%1,%2,%3}, {%4,%5,%6,%7}, {%8,%9}, {%0,%1,%2,%3};"
        : "+f"(c[0]), "+f"(c[1]), "+f"(c[2]), "+f"(c[3])
        : "r"(a[0]), "r"(a[1]), "r"(a[2]), "r"(a[3]), "r"(b[0]), "r"(b[1]));
}

template<int MODE>
__global__ void mma_gemm_kernel(const __nv_bfloat16* __restrict__ Ah, const __nv_bfloat16* __restrict__ Al,
                                const __nv_bfloat16* __restrict__ Bth, const __nv_bfloat16* __restrict__ Btl,
                                const float* __restrict__ bias, const float* __restrict__ add,
                                float* __restrict__ C,
                                __nv_bfloat16* __restrict__ Oh, __nv_bfloat16* __restrict__ Ol,
                                int M, int N, int K){
    __shared__ uint32 AsH[2][64][9], AsL[2][64][9];
    __shared__ uint32 BsH[2][128][9], BsL[2][128][9];
    int tid = threadIdx.x, lane = tid & 31, wid = tid >> 5;
    int g = lane >> 2, t4 = lane & 3;
    int warp_m = wid >> 1, warp_n = wid & 1;
    int m0 = blockIdx.y * 64, n0 = blockIdx.x * 128;
    int K2 = K >> 1;

    int ar[4], ac[4], br[8], bc[8];
    #pragma unroll
    for (int i = 0; i < 4; i++){ int w = tid + i*128; ar[i] = w >> 3; ac[i] = w & 7; }
    #pragma unroll
    for (int i = 0; i < 8; i++){ int w = tid + i*128; br[i] = w >> 3; bc[i] = w & 7; }

    uint32 pah[4], pal[4], pbh[8], pbl[8];
    #pragma unroll
    for (int i = 0; i < 4; i++){
        size_t rowoff = (size_t)(m0 + ar[i]) * K2;
        pah[i] = ((const uint32*)Ah)[rowoff + ac[i]];
        pal[i] = ((const uint32*)Al)[rowoff + ac[i]];
    }
    #pragma unroll
    for (int i = 0; i < 8; i++){
        size_t rowoff = (size_t)(n0 + br[i]) * K2;
        pbh[i] = ((const uint32*)Bth)[rowoff + bc[i]];
        pbl[i] = ((const uint32*)Btl)[rowoff + bc[i]];
    }
    #pragma unroll
    for (int i = 0; i < 4; i++){ AsH[0][ar[i]][ac[i]] = pah[i]; AsL[0][ar[i]][ac[i]] = pal[i]; }
    #pragma unroll
    for (int i = 0; i < 8; i++){ BsH[0][br[i]][bc[i]] = pbh[i]; BsL[0][br[i]][bc[i]] = pbl[i]; }
    __syncthreads();

    float acc[2][8][4];
    #pragma unroll
    for (int fm = 0; fm < 2; fm++)
        #pragma unroll
        for (int fn = 0; fn < 8; fn++)
            #pragma unroll
            for (int i = 0; i < 4; i++) acc[fm][fn][i] = 0.f;

    int nk = K >> 4;
    for (int kt = 0; kt < nk; kt++){
        int cur = kt & 1, nxt = cur ^ 1;
        if (kt + 1 < nk){
            int kw = (kt + 1) * 8;
            #pragma unroll
            for (int i = 0; i < 4; i++){
                size_t rowoff = (size_t)(m0 + ar[i]) * K2 + kw;
                pah[i] = ((const uint32*)Ah)[rowoff + ac[i]];
                pal[i] = ((const uint32*)Al)[rowoff + ac[i]];
            }
            #pragma unroll
            for (int i = 0; i < 8; i++){
                size_t rowoff = (size_t)(n0 + br[i]) * K2 + kw;
                pbh[i] = ((const uint32*)Bth)[rowoff + bc[i]];
                pbl[i] = ((const uint32*)Btl)[rowoff + bc[i]];
            }
        }
        uint32 ah[2][4], al[2][4], bh[8][2], bl[8][2];
        #pragma unroll
        for (int fm = 0; fm < 2; fm++){
            int r0 = warp_m*32 + fm*16 + g;
            ah[fm][0] = AsH[cur][r0][t4];     ah[fm][1] = AsH[cur][r0+8][t4];
            ah[fm][2] = AsH[cur][r0][t4+4];   ah[fm][3] = AsH[cur][r0+8][t4+4];
            al[fm][0] = AsL[cur][r0][t4];     al[fm][1] = AsL[cur][r0+8][t4];
            al[fm][2] = AsL[cur][r0][t4+4];   al[fm][3] = AsL[cur][r0+8][t4+4];
        }
        #pragma unroll
        for (int fn = 0; fn < 8; fn++){
            int r0 = warp_n*64 + fn*8 + g;
            bh[fn][0] = BsH[cur][r0][t4]; bh[fn][1] = BsH[cur][r0][t4+4];
            bl[fn][0] = BsL[cur][r0][t4]; bl[fn][1] = BsL[cur][r0][t4+4];
        }
        #pragma unroll
        for (int fn = 0; fn < 8; fn++)
            #pragma unroll
            for (int fm = 0; fm < 2; fm++){
                mma16816(acc[fm][fn], ah[fm], bh[fn]);
                mma16816(acc[fm][fn], ah[fm], bl[fn]);
                mma16816(acc[fm][fn], al[fm], bh[fn]);
            }
        if (kt + 1 < nk){
            #pragma unroll
            for (int i = 0; i < 4; i++){ AsH[nxt][ar[i]][ac[i]] = pah[i]; AsL[nxt][ar[i]][ac[i]] = pal[i]; }
            #pragma unroll
            for (int i = 0; i < 8; i++){ BsH[nxt][br[i]][bc[i]] = pbh[i]; BsL[nxt][br[i]][bc[i]] = pbl[i]; }
            __syncthreads();
        }
    }

    #pragma unroll
    for (int fm = 0; fm < 2; fm++){
        int m1 = m0 + warp_m*32 + fm*16 + g;
        int m2 = m1 + 8;
        #pragma unroll
        for (int fn = 0; fn < 8; fn++){
            int n = n0 + warp_n*64 + fn*8 + t4*2;
            float b0 = bias ? bias[n] : 0.f, b1 = bias ? bias[n+1] : 0.f;
            float c0 = acc[fm][fn][0] + b0;
            float c1 = acc[fm][fn][1] + b1;
            float c2 = acc[fm][fn][2] + b0;
            float c3 = acc[fm][fn][3] + b1;
            if (MODE == 0){
                if (add){
                    c0 += add[(size_t)m1*N + n];   c1 += add[(size_t)m1*N + n + 1];
                    c2 += add[(size_t)m2*N + n];   c3 += add[(size_t)m2*N + n + 1];
                }
                *(float2*)&C[(size_t)m1*N + n] = make_float2(c0, c1);
                *(float2*)&C[(size_t)m2*N + n] = make_float2(c2, c3);
            } else {
                c0 = 0.5f*c0*(1.0f + erff(c0*0.70710678118654752f));
                c1 = 0.5f*c1*(1.0f + erff(c1*0.70710678118654752f));
                c2 = 0.5f*c2*(1.0f + erff(c2*0.70710678118654752f));
                c3 = 0.5f*c3*(1.0f + erff(c3*0.70710678118654752f));
                __nv_bfloat16 h0,l0,h1,l1,h2,l2,h3,l3;
                bsplit(c0,h0,l0); bsplit(c1,h1,l1); bsplit(c2,h2,l2); bsplit(c3,h3,l3);
                __nv_bfloat162 hp1; hp1.x = h0; hp1.y = h1;
                __nv_bfloat162 lp1; lp1.x = l0; lp1.y = l1;
                __nv_bfloat162 hp2; hp2.x = h2; hp2.y = h3;
                __nv_bfloat162 lp2; lp2.x = l2; lp2.y = l3;
                *(__nv_bfloat162*)&Oh[(size_t)m1*N + n] = hp1;
                *(__nv_bfloat162*)&Ol[(size_t)m1*N + n] = lp1;
                *(__nv_bfloat162*)&Oh[(size_t)m2*N + n] = hp2;
                *(__nv_bfloat162*)&Ol[(size_t)m2*N + n] = lp2;
            }
        }
    }
}

// ---------------- fused cross-attention -------------------------------------
// Writes output split-bf16 into concat buffer cols [0:128).
#define QPW 8
#define JPAD 224
__global__ void attn_kernel(){
    extern __shared__ float sm[];
    float* Ks = sm;
    float* Vs = Ks + JPAD*65;
    float* Qs = Vs + JPAD*64;
    float* Pp = Qs + 8*QPW*64;
    int bh = blockIdx.y;
    int b = bh >> 1, h = bh & 1;
    int tid = threadIdx.x, lane = tid & 31, w = tid >> 5;
    for (int e = tid; e < JPAD*64; e += 256){
        int j = e >> 6, d = e & 63;
        float kv = 0.f, vv = 0.f;
        if (j < NSR){
            size_t base = ((size_t)b*NSR + j)*256 + h*64 + d;
            kv = g_kv[base]; vv = g_kv[base + 128];
        }
        Ks[j*65 + d] = kv;
        Vs[e] = vv;
    }
    int qbase = blockIdx.x * 64 + w * QPW;
    for (int e = lane; e < QPW*64; e += 32){
        int qi = e >> 6, d = e & 63;
        int gq = qbase + qi;
        Qs[(w*QPW + qi)*64 + d] = (gq < ND) ? g_q[((size_t)b*ND + gq)*128 + h*64 + d] : 0.f;
    }
    __syncthreads();

    float acc[QPW][7];
    #pragma unroll
    for (int qi = 0; qi < QPW; qi++)
        #pragma unroll
        for (int t = 0; t < 7; t++) acc[qi][t] = 0.f;

    for (int d = 0; d < 64; d++){
        float qv[QPW];
        #pragma unroll
        for (int qi = 0; qi < QPW; qi++) qv[qi] = Qs[(w*QPW + qi)*64 + d];
        #pragma unroll
        for (int t = 0; t < 7; t++){
            float kv = Ks[(lane + 32*t)*65 + d];
            #pragma unroll
            for (int qi = 0; qi < QPW; qi++) acc[qi][t] += qv[qi]*kv;
        }
    }
    const float scale = 0.17677669529663687f;
    float sums[QPW];
    #pragma unroll
    for (int qi = 0; qi < QPW; qi++){
        float mx = -1e30f;
        #pragma unroll
        for (int t = 0; t < 7; t++){
            int j = lane + 32*t;
            acc[qi][t] *= scale;
            if (j < NSR) mx = fmaxf(mx, acc[qi][t]);
        }
        mx = warp_max(mx);
        float s = 0.f;
        #pragma unroll
        for (int t = 0; t < 7; t++){
            int j = lane + 32*t;
            if (j < NSR){
                float e = expf(acc[qi][t] - mx);
                Pp[(w*QPW + qi)*196 + j] = e;
                s += e;
            }
        }
        sums[qi] = warp_sum(s);
    }
    __syncwarp();
    float o0[QPW] = {}, o1[QPW] = {};
    for (int j = 0; j < NSR; j++){
        float v0 = Vs[j*64 + lane], v1 = Vs[j*64 + lane + 32];
        #pragma unroll
        for (int qi = 0; qi < QPW; qi++){
            float p = Pp[(w*QPW + qi)*196 + j];
            o0[qi] += p*v0; o1[qi] += p*v1;
        }
    }
    #pragma unroll
    for (int qi = 0; qi < QPW; qi++){
        int gq = qbase + qi;
        if (gq < ND){
            size_t cb = ((size_t)b*ND + gq)*KCAT + h*64;
            float inv = 1.0f / sums[qi];
            __nv_bfloat16 hh, ll;
            bsplit(o0[qi]*inv, hh, ll); g_cath[cb + lane]      = hh; g_catl[cb + lane]      = ll;
            bsplit(o1[qi]*inv, hh, ll); g_cath[cb + lane + 32] = hh; g_catl[cb + lane + 32] = ll;
        }
    }
}

// ---------------- bilinear grid-sample of pos_embed, add into out -----------
__global__ void possample_kernel(const float* __restrict__ pe, float* __restrict__ out){
    int warp = (blockIdx.x * blockDim.x + threadIdx.x) >> 5;
    int lane = threadIdx.x & 31;
    if (warp >= Bv*ND) return;
    float px = g_posd[(size_t)warp*2], py = g_posd[(size_t)warp*2 + 1];
    float gx = px*2.f - 1.f, gy = py*2.f - 1.f;
    float ix = ((gx + 1.f)*56.f - 1.f)*0.5f;
    float iy = ((gy + 1.f)*56.f - 1.f)*0.5f;
    float x0 = floorf(ix), y0 = floorf(iy);
    float wx = ix - x0,   wy = iy - y0;
    float accv[4] = {};
    #pragma unroll
    for (int cy = 0; cy < 2; cy++){
        #pragma unroll
        for (int cx = 0; cx < 2; cx++){
            float xc = x0 + cx, yc = y0 + cy;
            float wgt = (cx ? wx : 1.f-wx) * (cy ? wy : 1.f-wy);
            bool valid = (xc >= 0.f) && (xc < 56.f) && (yc >= 0.f) && (yc < 56.f);
            float wv = valid ? wgt : 0.f;
            int xi = (int)fminf(fmaxf(xc, 0.f), 55.f);
            int yi = (int)fminf(fmaxf(yc, 0.f), 55.f);
            int lin = yi*56 + xi;
            #pragma unroll
            for (int r = 0; r < 4; r++)
                accv[r] += pe[(size_t)lin*128 + lane + 32*r] * wv;
        }
    }
    #pragma unroll
    for (int r = 0; r < 4; r++)
        out[(size_t)warp*128 + lane + 32*r] += accv[r];
}

// ---------------- launcher ---------------------------------------------------
extern "C" void kernel_launch(void* const* d_in, const int* in_sizes, int n_in,
                              void* d_out, int out_size){
    const float* x        = (const float*)d_in[0];
    const float* pos      = (const float*)d_in[1];
    const float* pos_embed= (const float*)d_in[2];
    const float* noise_u  = (const float*)d_in[3];
    const float* norm_g   = (const float*)d_in[4];
    const float* norm_b   = (const float*)d_in[5];
    const float* conf_w   = (const float*)d_in[6];
    const float* conf_b   = (const float*)d_in[7];
    const float* n1g      = (const float*)d_in[8];
    const float* n1b      = (const float*)d_in[9];
    const float* q_w      = (const float*)d_in[10];
    const float* k_w      = (const float*)d_in[11];
    const float* v_w      = (const float*)d_in[12];
    const float* proj_w   = (const float*)d_in[13];
    const float* proj_b   = (const float*)d_in[14];
    const float* sr_w     = (const float*)d_in[15];
    const float* sr_b     = (const float*)d_in[16];
    const float* srn_g    = (const float*)d_in[17];
    const float* srn_b    = (const float*)d_in[18];
    const float* fc_w     = (const float*)d_in[19];
    const float* fc_b     = (const float*)d_in[20];
    const float* n2g      = (const float*)d_in[21];
    const float* n2b      = (const float*)d_in[22];
    const float* fc1_w    = (const float*)d_in[23];
    const float* fc1_b    = (const float*)d_in[24];
    const float* fc2_w    = (const float*)d_in[25];
    const float* fc2_b    = (const float*)d_in[26];
    float* out = (float*)d_out;

    float *p_xs, *p_q, *p_kv, *p_x2, *p_biaspf;
    __nv_bfloat16 *p_xnh, *p_xnl, *p_xsh, *p_xsl, *p_cath, *p_catl;
    __nv_bfloat16 *p_xn2h, *p_xn2l, *p_hidh, *p_hidl;
    __nv_bfloat16 *p_w1h, *p_w1l, *p_w2h, *p_w2l, *p_wqh, *p_wql, *p_wkvh, *p_wkvl, *p_wpfh, *p_wpfl;
    cudaGetSymbolAddress((void**)&p_xs,    g_xs);
    cudaGetSymbolAddress((void**)&p_q,     g_q);
    cudaGetSymbolAddress((void**)&p_kv,    g_kv);
    cudaGetSymbolAddress((void**)&p_x2,    g_x2);
    cudaGetSymbolAddress((void**)&p_biaspf,g_biaspf);
    cudaGetSymbolAddress((void**)&p_xnh,   g_xnh);
    cudaGetSymbolAddress((void**)&p_xnl,   g_xnl);
    cudaGetSymbolAddress((void**)&p_xsh,   g_xsh);
    cudaGetSymbolAddress((void**)&p_xsl,   g_xsl);
    cudaGetSymbolAddress((void**)&p_cath,  g_cath);
    cudaGetSymbolAddress((void**)&p_catl,  g_catl);
    cudaGetSymbolAddress((void**)&p_xn2h,  g_xn2h);
    cudaGetSymbolAddress((void**)&p_xn2l,  g_xn2l);
    cudaGetSymbolAddress((void**)&p_hidh,  g_hidh);
    cudaGetSymbolAddress((void**)&p_hidl,  g_hidl);
    cudaGetSymbolAddress((void**)&p_w1h,   g_w1h);
    cudaGetSymbolAddress((void**)&p_w1l,   g_w1l);
    cudaGetSymbolAddress((void**)&p_w2h,   g_w2h);
    cudaGetSymbolAddress((void**)&p_w2l,   g_w2l);
    cudaGetSymbolAddress((void**)&p_wqh,   g_wqh);
    cudaGetSymbolAddress((void**)&p_wql,   g_wql);
    cudaGetSymbolAddress((void**)&p_wkvh,  g_wkvh);
    cudaGetSymbolAddress((void**)&p_wkvl,  g_wkvl);
    cudaGetSymbolAddress((void**)&p_wpfh,  g_wpfh);
    cudaGetSymbolAddress((void**)&p_wpfl,  g_wpfl);

    zero_kernel<<<4096, 256>>>();
    // weight prep (independent of data path)
    split_w_kernel<<<(DOUT*HIDN + 255)/256, 256>>>(fc1_w, p_w1h, p_w1l, DOUT, HIDN, DOUT, 0);
    split_w_kernel<<<(HIDN*DOUT + 255)/256, 256>>>(fc2_w, p_w2h, p_w2l, HIDN, DOUT, HIDN, 0);
    split_w_kernel<<<(Cv*DOUT + 255)/256, 256>>>(q_w, p_wqh, p_wql, Cv, DOUT, Cv, 0);
    split_w_kernel<<<(Cv*DOUT + 255)/256, 256>>>(k_w, p_wkvh, p_wkvl, Cv, DOUT, Cv, 0);
    split_w_kernel<<<(Cv*DOUT + 255)/256, 256>>>(v_w, p_wkvh + 128*Cv, p_wkvl + 128*Cv, Cv, DOUT, Cv, 0);
    split_w_kernel<<<(DOUT*DOUT + 255)/256, 256>>>(proj_w, p_wpfh, p_wpfl, DOUT, DOUT, KCAT, 0);
    split_w_kernel<<<(Cv*DOUT + 255)/256, 256>>>(fc_w, p_wpfh, p_wpfl, Cv, DOUT, KCAT, 128);
    biaspf_kernel<<<1, 128>>>(proj_b, fc_b);

    ln_scatter_kernel<<<(Bv*Nv + 7)/8, 256>>>(x, pos, n1g, n1b);
    score_kernel<<<(Bv*NS + 255)/256, 256>>>(x, noise_u, norm_g, norm_b, conf_w, conf_b);
    topk_kernel<<<Bv, 1024>>>();
    gather_ln_kernel<<<(Bv*ND + 7)/8, 256>>>(x, pos, n1g, n1b);
    blur_kernel<<<(Bv*Nv*Cv + 255)/256, 256>>>();
    srconv_kernel<<<196, 256>>>(sr_w, sr_b);
    ln64_split_kernel<<<(MSR + 7)/8, 256>>>(p_xs, p_xsh, p_xsl, srn_g, srn_b, MSR);

    // q = xn @ q_w ; [k|v] = xs @ [k_w|v_w]   (tensor cores, no bias)
    mma_gemm_kernel<0><<<dim3(1, MROWS/64), 128>>>(
        p_xnh, p_xnl, p_wqh, p_wql, nullptr, nullptr, p_q, nullptr, nullptr, MROWS, 128, 64);
    mma_gemm_kernel<0><<<dim3(2, MSR/64), 128>>>(
        p_xsh, p_xsl, p_wkvh, p_wkvl, nullptr, nullptr, p_kv, nullptr, nullptr, MSR, 256, 64);

    // fused attention -> concat buffer cols [0:128)
    size_t attn_smem = (size_t)(JPAD*65 + JPAD*64 + 8*QPW*64 + 8*QPW*196) * sizeof(float);
    cudaFuncSetAttribute(attn_kernel, cudaFuncAttributeMaxDynamicSharedMemorySize, (int)attn_smem);
    attn_kernel<<<dim3(14, Bv*2), 256, attn_smem>>>();

    // x2 = [oatt|xdown] @ [proj_w;fc_w] + (proj_b+fc_b)   (K=192)
    mma_gemm_kernel<0><<<dim3(1, MROWS/64), 128>>>(
        p_cath, p_catl, p_wpfh, p_wpfl, p_biaspf, nullptr, p_x2, nullptr, nullptr, MROWS, 128, KCAT);

    // LN2 -> split bf16 xn2
    ln128_split_kernel<<<(Bv*ND + 7)/8, 256>>>(p_x2, p_xn2h, p_xn2l, n2g, n2b, Bv*ND);

    // hid = gelu(xn2 @ fc1 + b1) -> split bf16 (tensor cores)
    mma_gemm_kernel<1><<<dim3(HIDN/128, MROWS/64), 128>>>(
        p_xn2h, p_xn2l, p_w1h, p_w1l, fc1_b, nullptr, nullptr, p_hidh, p_hidl,
        MROWS, HIDN, DOUT);
    // out = x2 + hid @ fc2 + b2 (tensor cores)
    mma_gemm_kernel<0><<<dim3(DOUT/128, MROWS/64), 128>>>(
        p_hidh, p_hidl, p_w2h, p_w2l, fc2_b, p_x2, out, nullptr, nullptr,
        MROWS, DOUT, HIDN);

    // out += grid_sample(pos_embed)
    possample_kernel<<<(Bv*ND + 7)/8, 256>>>(pos_embed, out);
}

// round 13
// speedup vs baseline: 1.6744x; 1.0781x over previous
#include <cuda_runtime.h>
#include <cuda_bf16.h>
#include <math.h>

typedef unsigned int uint32;

// Problem constants (fixed by setup_inputs)
#define Bv 64
#define Nv 3136
#define Cv 64
#define DOUT 128
#define Wv 56
#define NG 49
#define SAMPLE 784
#define ND 833            // NG + SAMPLE
#define NS 3087           // Nv - NG
#define NSR 196           // (56/4)^2
#define HIDN 512
#define MROWS (Bv*ND)     // 53312
#define MSR   (Bv*NSR)    // 12544
#define KCAT  192         // 128 (oatt) + 64 (xdown)

// ---------------- scratch (static device memory; allocation-free) ----------
__device__ float g_scores[Bv*NS];
__device__ int   g_idx  [Bv*SAMPLE];
__device__ float g_posd [Bv*ND*2];
__device__ float g_segf [Bv*Nv*Cv];
__device__ float g_cnt  [Bv*Nv];
__device__ float g_fmap [Bv*Nv*Cv];
__device__ float g_xs   [MSR*Cv];
__device__ float g_q    [MROWS*DOUT];
__device__ float g_kv   [MSR*256];
__device__ float g_x2   [MROWS*DOUT];
// bf16-split operands for tensor-core GEMMs
__device__ __align__(16) __nv_bfloat16 g_xnh[MROWS*Cv];
__device__ __align__(16) __nv_bfloat16 g_xnl[MROWS*Cv];
__device__ __align__(16) __nv_bfloat16 g_xsh[MSR*Cv];
__device__ __align__(16) __nv_bfloat16 g_xsl[MSR*Cv];
__device__ __align__(16) __nv_bfloat16 g_cath[(size_t)MROWS*KCAT];
__device__ __align__(16) __nv_bfloat16 g_catl[(size_t)MROWS*KCAT];
__device__ __align__(16) __nv_bfloat16 g_xn2h[MROWS*DOUT];
__device__ __align__(16) __nv_bfloat16 g_xn2l[MROWS*DOUT];
__device__ __align__(16) __nv_bfloat16 g_hidh[(size_t)MROWS*HIDN];
__device__ __align__(16) __nv_bfloat16 g_hidl[(size_t)MROWS*HIDN];
__device__ __align__(16) __nv_bfloat16 g_w1h[HIDN*DOUT];   // [n][k]
__device__ __align__(16) __nv_bfloat16 g_w1l[HIDN*DOUT];
__device__ __align__(16) __nv_bfloat16 g_w2h[DOUT*HIDN];
__device__ __align__(16) __nv_bfloat16 g_w2l[DOUT*HIDN];
__device__ __align__(16) __nv_bfloat16 g_wqh[DOUT*Cv];
__device__ __align__(16) __nv_bfloat16 g_wql[DOUT*Cv];
__device__ __align__(16) __nv_bfloat16 g_wkvh[256*Cv];
__device__ __align__(16) __nv_bfloat16 g_wkvl[256*Cv];
__device__ __align__(16) __nv_bfloat16 g_wpfh[DOUT*KCAT];
__device__ __align__(16) __nv_bfloat16 g_wpfl[DOUT*KCAT];
__device__ float g_biaspf[DOUT];

__device__ __forceinline__ float warp_sum(float v){
    #pragma unroll
    for (int o = 16; o; o >>= 1) v = __fadd_rn(v, __shfl_xor_sync(0xffffffffu, v, o));
    return v;
}
__device__ __forceinline__ float warp_max(float v){
    #pragma unroll
    for (int o = 16; o; o >>= 1) v = fmaxf(v, __shfl_xor_sync(0xffffffffu, v, o));
    return v;
}
__device__ __forceinline__ void bsplit(float v, __nv_bfloat16& h, __nv_bfloat16& l){
    h = __float2bfloat16(v);
    l = __float2bfloat16(v - __bfloat162float(h));
}

// ---------------- zero segf/cnt -------------------------------------------
__global__ void zero_kernel(){
    int stride = gridDim.x * blockDim.x;
    int t = blockIdx.x * blockDim.x + threadIdx.x;
    for (int i = t; i < Bv*Nv*Cv; i += stride) g_segf[i] = 0.f;
    for (int i = t; i < Bv*Nv;    i += stride) g_cnt[i]  = 0.f;
}

// ---------------- unified weight prep: transpose+split all weights ---------
// seg layout (element counts):
//  fc1 65536 | fc2 65536 | q 8192 | k 8192 | v 8192 | proj 16384 | fc 8192 | bias 128
__global__ void prep_kernel(const float* __restrict__ fc1_w, const float* __restrict__ fc2_w,
                            const float* __restrict__ q_w, const float* __restrict__ k_w,
                            const float* __restrict__ v_w, const float* __restrict__ proj_w,
                            const float* __restrict__ fc_w,
                            const float* __restrict__ proj_b, const float* __restrict__ fc_b){
    int t = blockIdx.x * blockDim.x + threadIdx.x;
    __nv_bfloat16 h, l;
    if (t < 65536){                      // fc1: K=128,N=512 -> w1[n*128+k]
        int n = t / DOUT, k = t % DOUT;
        bsplit(fc1_w[(size_t)k*HIDN + n], h, l);
        g_w1h[t] = h; g_w1l[t] = l; return;
    }
    t -= 65536;
    if (t < 65536){                      // fc2: K=512,N=128 -> w2[n*512+k]
        int n = t / HIDN, k = t % HIDN;
        bsplit(fc2_w[(size_t)k*DOUT + n], h, l);
        g_w2h[t] = h; g_w2l[t] = l; return;
    }
    t -= 65536;
    if (t < 8192){                       // q: K=64,N=128 -> wq[n*64+k]
        int n = t / Cv, k = t % Cv;
        bsplit(q_w[(size_t)k*DOUT + n], h, l);
        g_wqh[t] = h; g_wql[t] = l; return;
    }
    t -= 8192;
    if (t < 8192){                       // k -> wkv rows [0:128)
        int n = t / Cv, k = t % Cv;
        bsplit(k_w[(size_t)k*DOUT + n], h, l);
        g_wkvh[t] = h; g_wkvl[t] = l; return;
    }
    t -= 8192;
    if (t < 8192){                       // v -> wkv rows [128:256)
        int n = t / Cv, k = t % Cv;
        bsplit(v_w[(size_t)k*DOUT + n], h, l);
        g_wkvh[128*Cv + t] = h; g_wkvl[128*Cv + t] = l; return;
    }
    t -= 8192;
    if (t < 16384){                      // proj: K=128,N=128 -> wpf[n*192+k]
        int n = t / DOUT, k = t % DOUT;
        bsplit(proj_w[(size_t)k*DOUT + n], h, l);
        g_wpfh[(size_t)n*KCAT + k] = h; g_wpfl[(size_t)n*KCAT + k] = l; return;
    }
    t -= 16384;
    if (t < 8192){                       // fc: K=64,N=128 -> wpf[n*192+128+k]
        int n = t / Cv, k = t % Cv;
        bsplit(fc_w[(size_t)k*DOUT + n], h, l);
        g_wpfh[(size_t)n*KCAT + 128 + k] = h; g_wpfl[(size_t)n*KCAT + 128 + k] = l; return;
    }
    t -= 8192;
    if (t < DOUT) g_biaspf[t] = proj_b[t] + fc_b[t];
}

// ---------------- LN(x) -> scatter directly (token2map segment_sum) --------
__global__ void ln_scatter_kernel(const float* __restrict__ x, const float* __restrict__ pos,
                                  const float* __restrict__ n1g, const float* __restrict__ n1b){
    int warp = (blockIdx.x * blockDim.x + threadIdx.x) >> 5;
    int lane = threadIdx.x & 31;
    if (warp >= Bv*Nv) return;
    const float* xr = x + (size_t)warp * Cv;
    float v0 = xr[lane], v1 = xr[lane+32];
    float m = warp_sum(v0 + v1) * (1.0f/64.0f);
    float d0 = v0 - m, d1 = v1 - m;
    float var = warp_sum(d0*d0 + d1*d1) * (1.0f/64.0f);
    float rstd = rsqrtf(var + 1e-5f);
    float xsn0 = d0*rstd*n1g[lane]    + n1b[lane];
    float xsn1 = d1*rstd*n1g[lane+32] + n1b[lane+32];
    int b = warp / Nv;
    int p = 0;
    if (lane == 0){
        float px = fminf(fmaxf(pos[(size_t)warp*2],   0.f), 1.f) * 55.f;
        float py = fminf(fmaxf(pos[(size_t)warp*2+1], 0.f), 1.f) * 55.f;
        p = (int)rintf(px) + (int)rintf(py) * Wv;     // half-to-even like jnp.round
    }
    p = __shfl_sync(0xffffffffu, p, 0);
    size_t base = ((size_t)b*Nv + p)*64;
    atomicAdd(&g_segf[base + lane],      xsn0);
    atomicAdd(&g_segf[base + lane + 32], xsn1);
    if (lane == 0) atomicAdd(&g_cnt[b*Nv + p], 1.0f);
}

// ---------------- score path: XLA-CPU semantics, row cached in registers ----
__global__ void score_kernel(const float* __restrict__ x,
                             const float* __restrict__ noise_u,
                             const float* __restrict__ ng, const float* __restrict__ nb,
                             const float* __restrict__ cw, const float* __restrict__ cb){
    int t = blockIdx.x * blockDim.x + threadIdx.x;
    if (t >= Bv*NS) return;
    int b = t / NS, i = t % NS;
    int n = NG + i;
    const float4* xr4 = (const float4*)(x + ((size_t)b*Nv + n) * Cv);
    float r[64];
    #pragma unroll
    for (int q = 0; q < 16; q++){
        float4 v = xr4[q];
        r[q*4+0] = v.x; r[q*4+1] = v.y; r[q*4+2] = v.z; r[q*4+3] = v.w;
    }
    float s = 0.f;
    #pragma unroll
    for (int k = 0; k < 64; k++) s = __fadd_rn(s, r[k]);
    float m = __fdiv_rn(s, 64.0f);
    float vs = 0.f;
    #pragma unroll
    for (int k = 0; k < 64; k++){
        float d = __fsub_rn(r[k], m);
        vs = __fadd_rn(vs, __fmul_rn(d, d));
    }
    float var = __fdiv_rn(vs, 64.0f);
    float rstd = __fdiv_rn(1.0f, sqrtf(__fadd_rn(var, 1e-5f)));   // CPU rsqrt = 1/sqrt
    float c = 0.f;
    #pragma unroll
    for (int k = 0; k < 64; k++){
        float h = __fmul_rn(__fsub_rn(r[k], m), rstd);
        float tt = __fadd_rn(__fmul_rn(h, ng[k]), nb[k]);
        c = __fadd_rn(c, __fmul_rn(tt, cw[k]));
    }
    float u = noise_u[t];
    float a1 = __fadd_rn(u, 1e-6f);
    float l1 = (float)log((double)a1);
    float inner = __fadd_rn(-l1, 1e-6f);
    float l2 = (float)log((double)inner);
    float noise = -l2;
    g_scores[t] = __fadd_rn(__fadd_rn(c, cb[0]), noise);
}

// ---------------- exact jax top-k: bitonic sort of (score desc, idx asc) ---
__global__ void topk_kernel(){
    __shared__ unsigned long long keys[4096];
    int b = blockIdx.x, tid = threadIdx.x;
    for (int i = tid; i < 4096; i += 1024){
        unsigned long long kk = ~0ULL;
        if (i < NS){
            unsigned u = __float_as_uint(g_scores[(size_t)b*NS + i]);
            u = (u & 0x80000000u) ? ~u : (u | 0x80000000u);
            kk = ((unsigned long long)(~u) << 32) | (unsigned)i;
        }
        keys[i] = kk;
    }
    __syncthreads();
    for (int k = 2; k <= 4096; k <<= 1)
        for (int j = k >> 1; j > 0; j >>= 1){
            for (int t = tid; t < 4096; t += 1024){
                int ixj = t ^ j;
                if (ixj > t){
                    bool up = ((t & k) == 0);
                    unsigned long long a = keys[t], c = keys[ixj];
                    if ((a > c) == up){ keys[t] = c; keys[ixj] = a; }
                }
            }
            __syncthreads();
        }
    for (int i = tid; i < SAMPLE; i += 1024)
        g_idx[b*SAMPLE + i] = (int)(unsigned)(keys[i] & 0xFFFFFFFFULL);
}

// ---- gather: xdown split -> cat cols [128:192), xn split, pos_down --------
__global__ void gather_ln_kernel(const float* __restrict__ x, const float* __restrict__ pos,
                                 const float* __restrict__ n1g, const float* __restrict__ n1b){
    int warp = (blockIdx.x * blockDim.x + threadIdx.x) >> 5;
    int lane = threadIdx.x & 31;
    if (warp >= Bv*ND) return;
    int b = warp / ND, j = warp % ND;
    int n = (j < NG) ? j : (NG + g_idx[b*SAMPLE + (j - NG)]);
    const float* xr = x + ((size_t)b*Nv + n) * Cv;
    float v0 = xr[lane], v1 = xr[lane+32];
    {
        __nv_bfloat16 h, l;
        size_t cb = (size_t)warp*KCAT + 128;
        bsplit(v0, h, l); g_cath[cb + lane]      = h; g_catl[cb + lane]      = l;
        bsplit(v1, h, l); g_cath[cb + lane + 32] = h; g_catl[cb + lane + 32] = l;
    }
    float m = warp_sum(v0 + v1) * (1.0f/64.0f);
    float d0 = v0 - m, d1 = v1 - m;
    float var = warp_sum(d0*d0 + d1*d1) * (1.0f/64.0f);
    float rstd = rsqrtf(var + 1e-5f);
    float xn0 = d0*rstd*n1g[lane]    + n1b[lane];
    float xn1 = d1*rstd*n1g[lane+32] + n1b[lane+32];
    {
        __nv_bfloat16 h, l;
        bsplit(xn0, h, l); g_xnh[(size_t)warp*64 + lane]      = h; g_xnl[(size_t)warp*64 + lane]      = l;
        bsplit(xn1, h, l); g_xnh[(size_t)warp*64 + lane + 32] = h; g_xnl[(size_t)warp*64 + lane + 32] = l;
    }
    if (lane < 2) g_posd[(size_t)warp*2 + lane] = pos[((size_t)b*Nv + n)*2 + lane];
}

// ---------------- normalize + 3x3 gaussian reconstruct fused ----------------
__global__ void blur_kernel(){
    int t = blockIdx.x * blockDim.x + threadIdx.x;
    if (t >= Bv*Nv*Cv) return;
    int c = t & 63; int q = t >> 6; int hw = q % Nv; int b = q / Nv;
    int yy = hw / Wv, xx = hw % Wv;
    const float e1 = 0.88249690f, e2 = 0.77880078f;
    const float S  = 1.0f + 4.0f*(e1 + e2);
    const float wt[3] = {1.0f/S, e1/S, e2/S};
    float cc = g_cnt[b*Nv + hw];
    float maskc = cc > 0.f ? 1.f : 0.f;
    float featc = (g_segf[t] / (cc + 1e-6f)) * maskc;
    float bf = 0.f, bm = 0.f;
    #pragma unroll
    for (int dy = -1; dy <= 1; dy++){
        #pragma unroll
        for (int dx = -1; dx <= 1; dx++){
            int y2 = yy + dy, x2 = xx + dx;
            if (y2 >= 0 && y2 < Wv && x2 >= 0 && x2 < Wv){
                int hw2 = y2*Wv + x2;
                float cn = g_cnt[b*Nv + hw2];
                float mn = cn > 0.f ? 1.f : 0.f;
                float fn = (g_segf[((size_t)b*Nv + hw2)*64 + c] / (cn + 1e-6f)) * mn;
                float w = wt[dy*dy + dx*dx];
                bf += w * fn; bm += w * mn;
            }
        }
    }
    float fi = bf / (bm + 1e-6f);
    fi = (bm > 0.f) ? fi : 0.f;
    g_fmap[t] = featc + (1.f - maskc) * fi;
}

// ---------------- sr 4x4 stride-4 conv as tiled GEMM (fp32) -----------------
__global__ void srconv_kernel(const float* __restrict__ srw, const float* __restrict__ srb){
    __shared__ float As[16][64];
    __shared__ float Bs[16][64];
    int m0 = blockIdx.x * 64;
    int tid = threadIdx.x, tx = tid & 15, ty = tid >> 4;
    float acc[4][4] = {};
    for (int k0 = 0; k0 < 1024; k0 += 16){
        #pragma unroll
        for (int i = 0; i < 4; i++){
            int e = tid + i*256;
            int kk = e & 15, mm = e >> 4;
            int m = m0 + mm, k = k0 + kk;
            int b = m / NSR, s2 = m % NSR;
            int oy = s2 / 14, ox = s2 % 14;
            int kyx = k >> 6, ci = k & 63;
            int ky = kyx >> 2, kx = kyx & 3;
            As[kk][mm] = g_fmap[(((size_t)b*Nv) + (oy*4+ky)*Wv + (ox*4+kx))*64 + ci];
        }
        #pragma unroll
        for (int i = 0; i < 4; i++){
            int e = tid + i*256;
            int n = e & 63, kk = e >> 6;
            int k = k0 + kk;
            int kyx = k >> 6, ci = k & 63;
            Bs[kk][n] = srw[(size_t)n*1024 + ci*16 + kyx];
        }
        __syncthreads();
        #pragma unroll
        for (int kk = 0; kk < 16; kk++){
            float a[4], bb[4];
            #pragma unroll
            for (int i = 0; i < 4; i++) a[i] = As[kk][ty*4+i];
            #pragma unroll
            for (int j = 0; j < 4; j++) bb[j] = Bs[kk][tx*4+j];
            #pragma unroll
            for (int i = 0; i < 4; i++)
                #pragma unroll
                for (int j = 0; j < 4; j++) acc[i][j] += a[i]*bb[j];
        }
        __syncthreads();
    }
    #pragma unroll
    for (int i = 0; i < 4; i++)
        #pragma unroll
        for (int j = 0; j < 4; j++){
            int m = m0 + ty*4 + i, n = tx*4 + j;
            g_xs[(size_t)m*64 + n] = acc[i][j] + srb[n];
        }
}

// ---------------- ln64 -> split bf16 (feeds k/v mma) ------------------------
__global__ void ln64_split_kernel(const float* __restrict__ in,
                                  __nv_bfloat16* __restrict__ oh, __nv_bfloat16* __restrict__ ol,
                                  const float* __restrict__ g, const float* __restrict__ b, int rows){
    int warp = (blockIdx.x * blockDim.x + threadIdx.x) >> 5;
    int lane = threadIdx.x & 31;
    if (warp >= rows) return;
    const float* xr = in + (size_t)warp*64;
    float v0 = xr[lane], v1 = xr[lane+32];
    float m = warp_sum(v0+v1) * (1.0f/64.0f);
    float d0 = v0-m, d1 = v1-m;
    float rstd = rsqrtf(warp_sum(d0*d0+d1*d1)*(1.0f/64.0f) + 1e-5f);
    float o0 = d0*rstd*g[lane]    + b[lane];
    float o1 = d1*rstd*g[lane+32] + b[lane+32];
    __nv_bfloat16 h, l;
    bsplit(o0, h, l); oh[(size_t)warp*64 + lane]      = h; ol[(size_t)warp*64 + lane]      = l;
    bsplit(o1, h, l); oh[(size_t)warp*64 + lane + 32] = h; ol[(size_t)warp*64 + lane + 32] = l;
}

// ---------------- ln128 -> split bf16 (feeds fc1 mma) -----------------------
__global__ void ln128_split_kernel(const float* __restrict__ in,
                                   __nv_bfloat16* __restrict__ oh, __nv_bfloat16* __restrict__ ol,
                                   const float* __restrict__ g, const float* __restrict__ b, int rows){
    int warp = (blockIdx.x * blockDim.x + threadIdx.x) >> 5;
    int lane = threadIdx.x & 31;
    if (warp >= rows) return;
    const float* xr = in + (size_t)warp*128;
    float v[4]; float s = 0.f;
    #pragma unroll
    for (int r = 0; r < 4; r++){ v[r] = xr[lane + 32*r]; s += v[r]; }
    float m = warp_sum(s) * (1.0f/128.0f);
    float vs = 0.f;
    #pragma unroll
    for (int r = 0; r < 4; r++){ v[r] -= m; vs += v[r]*v[r]; }
    float rstd = rsqrtf(warp_sum(vs)*(1.0f/128.0f) + 1e-5f);
    #pragma unroll
    for (int r = 0; r < 4; r++){
        int d = lane + 32*r;
        float o = v[r]*rstd*g[d] + b[d];
        __nv_bfloat16 h, l; bsplit(o, h, l);
        oh[(size_t)warp*128 + d] = h;
        ol[(size_t)warp*128 + d] = l;
    }
}

// ---------------- bf16x3 tensor-core GEMM (mma.sync m16n8k16) ---------------
__device__ __forceinline__ void mma16816(float* c, const uint32* a, const uint32* b){
    asm volatile("mma.sync.aligned.m16n8k16.row.col.f32.bf16.bf16.f32 "
        "{%0,%1,%2,%3}, {%4,%5,%6,%7}, {%8,%9}, {%0,%1,%2,%3};"
        : "+f"(c[0]), "+f"(c[1]), "+f"(c[2]), "+f"(c[3])
        : "r"(a[0]), "r"(a[1]), "r"(a[2]), "r"(a[3]), "r"(b[0]), "r"(b[1]));
}

template<int MODE>
__global__ void mma_gemm_kernel(const __nv_bfloat16* __restrict__ Ah, const __nv_bfloat16* __restrict__ Al,
                                const __nv_bfloat16* __restrict__ Bth, const __nv_bfloat16* __restrict__ Btl,
                                const float* __restrict__ bias, const float* __restrict__ add,
                                float* __restrict__ C,
                                __nv_bfloat16* __restrict__ Oh, __nv_bfloat16* __restrict__ Ol,
                                int M, int N, int K){
    __shared__ uint32 AsH[2][64][9], AsL[2][64][9];
    __shared__ uint32 BsH[2][128][9], BsL[2][128][9];
    int tid = threadIdx.x, lane = tid & 31, wid = tid >> 5;
    int g = lane >> 2, t4 = lane & 3;
    int warp_m = wid >> 1, warp_n = wid & 1;
    int m0 = blockIdx.y * 64, n0 = blockIdx.x * 128;
    int K2 = K >> 1;

    int ar[4], ac[4], br[8], bc[8];
    #pragma unroll
    for (int i = 0; i < 4; i++){ int w = tid + i*128; ar[i] = w >> 3; ac[i] = w & 7; }
    #pragma unroll
    for (int i = 0; i < 8; i++){ int w = tid + i*128; br[i] = w >> 3; bc[i] = w & 7; }

    uint32 pah[4], pal[4], pbh[8], pbl[8];
    #pragma unroll
    for (int i = 0; i < 4; i++){
        size_t rowoff = (size_t)(m0 + ar[i]) * K2;
        pah[i] = ((const uint32*)Ah)[rowoff + ac[i]];
        pal[i] = ((const uint32*)Al)[rowoff + ac[i]];
    }
    #pragma unroll
    for (int i = 0; i < 8; i++){
        size_t rowoff = (size_t)(n0 + br[i]) * K2;
        pbh[i] = ((const uint32*)Bth)[rowoff + bc[i]];
        pbl[i] = ((const uint32*)Btl)[rowoff + bc[i]];
    }
    #pragma unroll
    for (int i = 0; i < 4; i++){ AsH[0][ar[i]][ac[i]] = pah[i]; AsL[0][ar[i]][ac[i]] = pal[i]; }
    #pragma unroll
    for (int i = 0; i < 8; i++){ BsH[0][br[i]][bc[i]] = pbh[i]; BsL[0][br[i]][bc[i]] = pbl[i]; }
    __syncthreads();

    float acc[2][8][4];
    #pragma unroll
    for (int fm = 0; fm < 2; fm++)
        #pragma unroll
        for (int fn = 0; fn < 8; fn++)
            #pragma unroll
            for (int i = 0; i < 4; i++) acc[fm][fn][i] = 0.f;

    int nk = K >> 4;
    for (int kt = 0; kt < nk; kt++){
        int cur = kt & 1, nxt = cur ^ 1;
        if (kt + 1 < nk){
            int kw = (kt + 1) * 8;
            #pragma unroll
            for (int i = 0; i < 4; i++){
                size_t rowoff = (size_t)(m0 + ar[i]) * K2 + kw;
                pah[i] = ((const uint32*)Ah)[rowoff + ac[i]];
                pal[i] = ((const uint32*)Al)[rowoff + ac[i]];
            }
            #pragma unroll
            for (int i = 0; i < 8; i++){
                size_t rowoff = (size_t)(n0 + br[i]) * K2 + kw;
                pbh[i] = ((const uint32*)Bth)[rowoff + bc[i]];
                pbl[i] = ((const uint32*)Btl)[rowoff + bc[i]];
            }
        }
        uint32 ah[2][4], al[2][4], bh[8][2], bl[8][2];
        #pragma unroll
        for (int fm = 0; fm < 2; fm++){
            int r0 = warp_m*32 + fm*16 + g;
            ah[fm][0] = AsH[cur][r0][t4];     ah[fm][1] = AsH[cur][r0+8][t4];
            ah[fm][2] = AsH[cur][r0][t4+4];   ah[fm][3] = AsH[cur][r0+8][t4+4];
            al[fm][0] = AsL[cur][r0][t4];     al[fm][1] = AsL[cur][r0+8][t4];
            al[fm][2] = AsL[cur][r0][t4+4];   al[fm][3] = AsL[cur][r0+8][t4+4];
        }
        #pragma unroll
        for (int fn = 0; fn < 8; fn++){
            int r0 = warp_n*64 + fn*8 + g;
            bh[fn][0] = BsH[cur][r0][t4]; bh[fn][1] = BsH[cur][r0][t4+4];
            bl[fn][0] = BsL[cur][r0][t4]; bl[fn][1] = BsL[cur][r0][t4+4];
        }
        #pragma unroll
        for (int fn = 0; fn < 8; fn++)
            #pragma unroll
            for (int fm = 0; fm < 2; fm++){
                mma16816(acc[fm][fn], ah[fm], bh[fn]);
                mma16816(acc[fm][fn], ah[fm], bl[fn]);
                mma16816(acc[fm][fn], al[fm], bh[fn]);
            }
        if (kt + 1 < nk){
            #pragma unroll
            for (int i = 0; i < 4; i++){ AsH[nxt][ar[i]][ac[i]] = pah[i]; AsL[nxt][ar[i]][ac[i]] = pal[i]; }
            #pragma unroll
            for (int i = 0; i < 8; i++){ BsH[nxt][br[i]][bc[i]] = pbh[i]; BsL[nxt][br[i]][bc[i]] = pbl[i]; }
            __syncthreads();
        }
    }

    #pragma unroll
    for (int fm = 0; fm < 2; fm++){
        int m1 = m0 + warp_m*32 + fm*16 + g;
        int m2 = m1 + 8;
        #pragma unroll
        for (int fn = 0; fn < 8; fn++){
            int n = n0 + warp_n*64 + fn*8 + t4*2;
            float b0 = bias ? bias[n] : 0.f, b1 = bias ? bias[n+1] : 0.f;
            float c0 = acc[fm][fn][0] + b0;
            float c1 = acc[fm][fn][1] + b1;
            float c2 = acc[fm][fn][2] + b0;
            float c3 = acc[fm][fn][3] + b1;
            if (MODE == 0){
                if (add){
                    c0 += add[(size_t)m1*N + n];   c1 += add[(size_t)m1*N + n + 1];
                    c2 += add[(size_t)m2*N + n];   c3 += add[(size_t)m2*N + n + 1];
                }
                *(float2*)&C[(size_t)m1*N + n] = make_float2(c0, c1);
                *(float2*)&C[(size_t)m2*N + n] = make_float2(c2, c3);
            } else {
                c0 = 0.5f*c0*(1.0f + erff(c0*0.70710678118654752f));
                c1 = 0.5f*c1*(1.0f + erff(c1*0.70710678118654752f));
                c2 = 0.5f*c2*(1.0f + erff(c2*0.70710678118654752f));
                c3 = 0.5f*c3*(1.0f + erff(c3*0.70710678118654752f));
                __nv_bfloat16 h0,l0,h1,l1,h2,l2,h3,l3;
                bsplit(c0,h0,l0); bsplit(c1,h1,l1); bsplit(c2,h2,l2); bsplit(c3,h3,l3);
                __nv_bfloat162 hp1; hp1.x = h0; hp1.y = h1;
                __nv_bfloat162 lp1; lp1.x = l0; lp1.y = l1;
                __nv_bfloat162 hp2; hp2.x = h2; hp2.y = h3;
                __nv_bfloat162 lp2; lp2.x = l2; lp2.y = l3;
                *(__nv_bfloat162*)&Oh[(size_t)m1*N + n] = hp1;
                *(__nv_bfloat162*)&Ol[(size_t)m1*N + n] = lp1;
                *(__nv_bfloat162*)&Oh[(size_t)m2*N + n] = hp2;
                *(__nv_bfloat162*)&Ol[(size_t)m2*N + n] = lp2;
            }
        }
    }
}

// ---------------- fused cross-attention (512 threads, 4 q per warp) ---------
// Writes output split-bf16 into concat buffer cols [0:128).
#define QPW 4
#define NWARP 16
#define JPAD 224
__global__ void attn_kernel(){
    extern __shared__ float sm[];
    float* Ks = sm;                          // [224][65]
    float* Vs = Ks + JPAD*65;                // [224][64]
    float* Qs = Vs + JPAD*64;                // [64][64]
    float* Pp = Qs + 64*64;                  // [64][196]
    int bh = blockIdx.y;
    int b = bh >> 1, h = bh & 1;
    int tid = threadIdx.x, lane = tid & 31, w = tid >> 5;
    for (int e = tid; e < JPAD*64; e += 512){
        int j = e >> 6, d = e & 63;
        float kv = 0.f, vv = 0.f;
        if (j < NSR){
            size_t base = ((size_t)b*NSR + j)*256 + h*64 + d;
            kv = g_kv[base]; vv = g_kv[base + 128];
        }
        Ks[j*65 + d] = kv;
        Vs[e] = vv;
    }
    int qbase = blockIdx.x * 64 + w * QPW;
    for (int e = lane; e < QPW*64; e += 32){
        int qi = e >> 6, d = e & 63;
        int gq = qbase + qi;
        Qs[(w*QPW + qi)*64 + d] = (gq < ND) ? g_q[((size_t)b*ND + gq)*128 + h*64 + d] : 0.f;
    }
    __syncthreads();

    float acc[QPW][7];
    #pragma unroll
    for (int qi = 0; qi < QPW; qi++)
        #pragma unroll
        for (int t = 0; t < 7; t++) acc[qi][t] = 0.f;

    for (int d = 0; d < 64; d++){
        float qv[QPW];
        #pragma unroll
        for (int qi = 0; qi < QPW; qi++) qv[qi] = Qs[(w*QPW + qi)*64 + d];
        #pragma unroll
        for (int t = 0; t < 7; t++){
            float kv = Ks[(lane + 32*t)*65 + d];
            #pragma unroll
            for (int qi = 0; qi < QPW; qi++) acc[qi][t] += qv[qi]*kv;
        }
    }
    const float scale = 0.17677669529663687f;
    float sums[QPW];
    #pragma unroll
    for (int qi = 0; qi < QPW; qi++){
        float mx = -1e30f;
        #pragma unroll
        for (int t = 0; t < 7; t++){
            int j = lane + 32*t;
            acc[qi][t] *= scale;
            if (j < NSR) mx = fmaxf(mx, acc[qi][t]);
        }
        mx = warp_max(mx);
        float s = 0.f;
        #pragma unroll
        for (int t = 0; t < 7; t++){
            int j = lane + 32*t;
            if (j < NSR){
                float e = expf(acc[qi][t] - mx);
                Pp[(w*QPW + qi)*196 + j] = e;
                s += e;
            }
        }
        sums[qi] = warp_sum(s);
    }
    __syncwarp();
    float o0[QPW] = {}, o1[QPW] = {};
    for (int j = 0; j < NSR; j++){
        float v0 = Vs[j*64 + lane], v1 = Vs[j*64 + lane + 32];
        #pragma unroll
        for (int qi = 0; qi < QPW; qi++){
            float p = Pp[(w*QPW + qi)*196 + j];
            o0[qi] += p*v0; o1[qi] += p*v1;
        }
    }
    #pragma unroll
    for (int qi = 0; qi < QPW; qi++){
        int gq = qbase + qi;
        if (gq < ND){
            size_t cb = ((size_t)b*ND + gq)*KCAT + h*64;
            float inv = 1.0f / sums[qi];
            __nv_bfloat16 hh, ll;
            bsplit(o0[qi]*inv, hh, ll); g_cath[cb + lane]      = hh; g_catl[cb + lane]      = ll;
            bsplit(o1[qi]*inv, hh, ll); g_cath[cb + lane + 32] = hh; g_catl[cb + lane + 32] = ll;
        }
    }
}

// ---------------- bilinear grid-sample of pos_embed, add into out -----------
__global__ void possample_kernel(const float* __restrict__ pe, float* __restrict__ out){
    int warp = (blockIdx.x * blockDim.x + threadIdx.x) >> 5;
    int lane = threadIdx.x & 31;
    if (warp >= Bv*ND) return;
    float px = g_posd[(size_t)warp*2], py = g_posd[(size_t)warp*2 + 1];
    float gx = px*2.f - 1.f, gy = py*2.f - 1.f;
    float ix = ((gx + 1.f)*56.f - 1.f)*0.5f;
    float iy = ((gy + 1.f)*56.f - 1.f)*0.5f;
    float x0 = floorf(ix), y0 = floorf(iy);
    float wx = ix - x0,   wy = iy - y0;
    float accv[4] = {};
    #pragma unroll
    for (int cy = 0; cy < 2; cy++){
        #pragma unroll
        for (int cx = 0; cx < 2; cx++){
            float xc = x0 + cx, yc = y0 + cy;
            float wgt = (cx ? wx : 1.f-wx) * (cy ? wy : 1.f-wy);
            bool valid = (xc >= 0.f) && (xc < 56.f) && (yc >= 0.f) && (yc < 56.f);
            float wv = valid ? wgt : 0.f;
            int xi = (int)fminf(fmaxf(xc, 0.f), 55.f);
            int yi = (int)fminf(fmaxf(yc, 0.f), 55.f);
            int lin = yi*56 + xi;
            #pragma unroll
            for (int r = 0; r < 4; r++)
                accv[r] += pe[(size_t)lin*128 + lane + 32*r] * wv;
        }
    }
    #pragma unroll
    for (int r = 0; r < 4; r++)
        out[(size_t)warp*128 + lane + 32*r] += accv[r];
}

// ---------------- launcher ---------------------------------------------------
extern "C" void kernel_launch(void* const* d_in, const int* in_sizes, int n_in,
                              void* d_out, int out_size){
    const float* x        = (const float*)d_in[0];
    const float* pos      = (const float*)d_in[1];
    const float* pos_embed= (const float*)d_in[2];
    const float* noise_u  = (const float*)d_in[3];
    const float* norm_g   = (const float*)d_in[4];
    const float* norm_b   = (const float*)d_in[5];
    const float* conf_w   = (const float*)d_in[6];
    const float* conf_b   = (const float*)d_in[7];
    const float* n1g      = (const float*)d_in[8];
    const float* n1b      = (const float*)d_in[9];
    const float* q_w      = (const float*)d_in[10];
    const float* k_w      = (const float*)d_in[11];
    const float* v_w      = (const float*)d_in[12];
    const float* proj_w   = (const float*)d_in[13];
    const float* proj_b   = (const float*)d_in[14];
    const float* sr_w     = (const float*)d_in[15];
    const float* sr_b     = (const float*)d_in[16];
    const float* srn_g    = (const float*)d_in[17];
    const float* srn_b    = (const float*)d_in[18];
    const float* fc_w     = (const float*)d_in[19];
    const float* fc_b     = (const float*)d_in[20];
    const float* n2g      = (const float*)d_in[21];
    const float* n2b      = (const float*)d_in[22];
    const float* fc1_w    = (const float*)d_in[23];
    const float* fc1_b    = (const float*)d_in[24];
    const float* fc2_w    = (const float*)d_in[25];
    const float* fc2_b    = (const float*)d_in[26];
    float* out = (float*)d_out;

    float *p_xs, *p_q, *p_kv, *p_x2, *p_biaspf;
    __nv_bfloat16 *p_xnh, *p_xnl, *p_xsh, *p_xsl, *p_cath, *p_catl;
    __nv_bfloat16 *p_xn2h, *p_xn2l, *p_hidh, *p_hidl;
    __nv_bfloat16 *p_w1h, *p_w1l, *p_w2h, *p_w2l, *p_wqh, *p_wql, *p_wkvh, *p_wkvl, *p_wpfh, *p_wpfl;
    cudaGetSymbolAddress((void**)&p_xs,    g_xs);
    cudaGetSymbolAddress((void**)&p_q,     g_q);
    cudaGetSymbolAddress((void**)&p_kv,    g_kv);
    cudaGetSymbolAddress((void**)&p_x2,    g_x2);
    cudaGetSymbolAddress((void**)&p_biaspf,g_biaspf);
    cudaGetSymbolAddress((void**)&p_xnh,   g_xnh);
    cudaGetSymbolAddress((void**)&p_xnl,   g_xnl);
    cudaGetSymbolAddress((void**)&p_xsh,   g_xsh);
    cudaGetSymbolAddress((void**)&p_xsl,   g_xsl);
    cudaGetSymbolAddress((void**)&p_cath,  g_cath);
    cudaGetSymbolAddress((void**)&p_catl,  g_catl);
    cudaGetSymbolAddress((void**)&p_xn2h,  g_xn2h);
    cudaGetSymbolAddress((void**)&p_xn2l,  g_xn2l);
    cudaGetSymbolAddress((void**)&p_hidh,  g_hidh);
    cudaGetSymbolAddress((void**)&p_hidl,  g_hidl);
    cudaGetSymbolAddress((void**)&p_w1h,   g_w1h);
    cudaGetSymbolAddress((void**)&p_w1l,   g_w1l);
    cudaGetSymbolAddress((void**)&p_w2h,   g_w2h);
    cudaGetSymbolAddress((void**)&p_w2l,   g_w2l);
    cudaGetSymbolAddress((void**)&p_wqh,   g_wqh);
    cudaGetSymbolAddress((void**)&p_wql,   g_wql);
    cudaGetSymbolAddress((void**)&p_wkvh,  g_wkvh);
    cudaGetSymbolAddress((void**)&p_wkvl,  g_wkvl);
    cudaGetSymbolAddress((void**)&p_wpfh,  g_wpfh);
    cudaGetSymbolAddress((void**)&p_wpfl,  g_wpfl);

    zero_kernel<<<4096, 256>>>();
    prep_kernel<<<(180288 + 255)/256, 256>>>(fc1_w, fc2_w, q_w, k_w, v_w, proj_w, fc_w, proj_b, fc_b);

    ln_scatter_kernel<<<(Bv*Nv + 7)/8, 256>>>(x, pos, n1g, n1b);
    score_kernel<<<(Bv*NS + 255)/256, 256>>>(x, noise_u, norm_g, norm_b, conf_w, conf_b);
    topk_kernel<<<Bv, 1024>>>();
    gather_ln_kernel<<<(Bv*ND + 7)/8, 256>>>(x, pos, n1g, n1b);
    blur_kernel<<<(Bv*Nv*Cv + 255)/256, 256>>>();
    srconv_kernel<<<196, 256>>>(sr_w, sr_b);
    ln64_split_kernel<<<(MSR + 7)/8, 256>>>(p_xs, p_xsh, p_xsl, srn_g, srn_b, MSR);

    // q = xn @ q_w ; [k|v] = xs @ [k_w|v_w]   (tensor cores, no bias)
    mma_gemm_kernel<0><<<dim3(1, MROWS/64), 128>>>(
        p_xnh, p_xnl, p_wqh, p_wql, nullptr, nullptr, p_q, nullptr, nullptr, MROWS, 128, 64);
    mma_gemm_kernel<0><<<dim3(2, MSR/64), 128>>>(
        p_xsh, p_xsl, p_wkvh, p_wkvl, nullptr, nullptr, p_kv, nullptr, nullptr, MSR, 256, 64);

    // fused attention -> concat buffer cols [0:128)
    size_t attn_smem = (size_t)(JPAD*65 + JPAD*64 + 64*64 + 64*196) * sizeof(float);
    cudaFuncSetAttribute(attn_kernel, cudaFuncAttributeMaxDynamicSharedMemorySize, (int)attn_smem);
    attn_kernel<<<dim3(14, Bv*2), 512, attn_smem>>>();

    // x2 = [oatt|xdown] @ [proj_w;fc_w] + (proj_b+fc_b)   (K=192)
    mma_gemm_kernel<0><<<dim3(1, MROWS/64), 128>>>(
        p_cath, p_catl, p_wpfh, p_wpfl, p_biaspf, nullptr, p_x2, nullptr, nullptr, MROWS, 128, KCAT);

    // LN2 -> split bf16 xn2
    ln128_split_kernel<<<(Bv*ND + 7)/8, 256>>>(p_x2, p_xn2h, p_xn2l, n2g, n2b, Bv*ND);

    // hid = gelu(xn2 @ fc1 + b1) -> split bf16 (tensor cores)
    mma_gemm_kernel<1><<<dim3(HIDN/128, MROWS/64), 128>>>(
        p_xn2h, p_xn2l, p_w1h, p_w1l, fc1_b, nullptr, nullptr, p_hidh, p_hidl,
        MROWS, HIDN, DOUT);
    // out = x2 + hid @ fc2 + b2 (tensor cores)
    mma_gemm_kernel<0><<<dim3(DOUT/128, MROWS/64), 128>>>(
        p_hidh, p_hidl, p_w2h, p_w2l, fc2_b, p_x2, out, nullptr, nullptr,
        MROWS, DOUT, HIDN);

    // out += grid_sample(pos_embed)
    possample_kernel<<<(Bv*ND + 7)/8, 256>>>(pos_embed, out);
}